// round 9
// baseline (speedup 1.0000x reference)
#include <cuda_runtime.h>
#include <mma.h>
#include <cstdint>
#include <math.h>

using namespace nvcuda;

// ---------------------------------------------------------------------------
// SelectiveSSM. B=4, L=1024, DM=64, DS=DI=128.
// Key change vs R8: Abar = mean_i exp(delta_i*A_is) computed via separable
// 4th-order Taylor => tensor-core GEMM:
//   Abar = 1 + sum_k (D_k @ M_k),  D_k = delta^k [4096x128], M_k = A^k/(128 k!)
// KP: projections (gate, delta->powers, Bm, Cm, x_pool); block 256 builds M.
// KE: per chunk: wmma tf32 GEMM [16x512]@[512x128] -> Abar; segment scan
//     -> cc, ch, P, Q.
// KB: 1 block: 64-chunk prefix scan -> H.
// KC: y = sum_s(ch + cc*H), silu(gate), W_out GEMV, residual, LayerNorm.
// ---------------------------------------------------------------------------

#define NB    4
#define NL    1024
#define NROW  4096
#define NCH   64
#define TC    16
#define LOG2E 1.4426950408889634f
#define LN2   0.6931471805599453f

__device__ float g_gate[NROW * 128];
__device__ float g_Dp  [NROW * 512];   // delta powers: [row][k*128+i] = d_i^(k+1)
__device__ float g_M   [512 * 128];    // [k*128+i][s] = A_is^(k+1)/(128*(k+1)!)
__device__ float g_bm  [NROW * 128];
__device__ float g_c   [NROW * 128];
__device__ float g_pool[NROW];
__device__ float g_cc  [NROW * 128];
__device__ float g_ch  [NROW * 128];
__device__ float g_P   [NB * NCH * 128];
__device__ float g_Q   [NB * NCH * 128];
__device__ float g_H   [NB * NCH * 128];

__device__ __forceinline__ float ex2f(float v) {
    float r;
    asm("ex2.approx.ftz.f32 %0, %1;" : "=f"(r) : "f"(v));
    return r;
}
__device__ __forceinline__ float lg2f(float v) {
    float r;
    asm("lg2.approx.ftz.f32 %0, %1;" : "=f"(r) : "f"(v));
    return r;
}

// ---------------------------------------------------------------------------
// KP: 257 blocks x 512 threads. Blocks 0..255: projections for one chunk.
//     Block 256: build g_M from A.
// ---------------------------------------------------------------------------
__global__ __launch_bounds__(512) void kp(
    const float* __restrict__ x,   const float* __restrict__ Win,
    const float* __restrict__ Wd,  const float* __restrict__ bd,
    const float* __restrict__ WB,  const float* __restrict__ bB,
    const float* __restrict__ WC,  const float* __restrict__ bC,
    const float* __restrict__ A) {
    int tid = threadIdx.x;

    if (blockIdx.x == 256) {
        // M_k[i][s] = A^k / (128*k!), k = 1..4
        for (int e = tid; e < 16384; e += 512) {
            float Av = A[e];
            float A2 = Av * Av;
            g_M[e]          = Av * (1.0f / 128.0f);
            g_M[16384 + e]  = A2 * (1.0f / 256.0f);
            g_M[32768 + e]  = A2 * Av * (1.0f / 768.0f);
            g_M[49152 + e]  = A2 * A2 * (1.0f / 3072.0f);
        }
        return;
    }

    __shared__ __align__(16) float xs[TC * 64];
    __shared__ float psum[8 * 64];
    __shared__ float wpool[64];

    int row0 = blockIdx.x * TC;

    for (int i = tid; i < TC * 64; i += 512) xs[i] = x[row0 * 64 + i];
    {
        int d = tid & 63, part = tid >> 6;
        float s = 0.f;
        const float* p = Win + part * 16 * 64 + d;
#pragma unroll
        for (int i = 0; i < 16; i++) s += p[i * 64];
        psum[part * 64 + d] = s;
    }
    __syncthreads();

    if (tid < 64) {
        float s = 0.f;
#pragma unroll
        for (int p = 0; p < 8; p++) s += psum[p * 64 + tid];
        wpool[tid] = s * (1.0f / 128.0f);
    }

    int mode = tid >> 7, fo = tid & 127;
    const float* wrow;
    float bias = 0.f;
    if (mode == 0)      { wrow = Win + (128 + fo) * 64; }
    else if (mode == 1) { wrow = Wd + fo * 64; bias = bd[fo]; }
    else if (mode == 2) { wrow = WB + fo * 64; bias = bB[fo]; }
    else                { wrow = WC + fo * 64; bias = bC[fo]; }
    const float4* w4 = (const float4*)wrow;

    float acc[TC];
#pragma unroll
    for (int r = 0; r < TC; r++) acc[r] = 0.f;
#pragma unroll
    for (int d4 = 0; d4 < 16; d4++) {
        float4 wv = __ldg(&w4[d4]);
#pragma unroll
        for (int r = 0; r < TC; r++) {
            float4 xv = *(const float4*)(xs + r * 64 + d4 * 4);
            acc[r] = fmaf(wv.x, xv.x, acc[r]);
            acc[r] = fmaf(wv.y, xv.y, acc[r]);
            acc[r] = fmaf(wv.z, xv.z, acc[r]);
            acc[r] = fmaf(wv.w, xv.w, acc[r]);
        }
    }
#pragma unroll
    for (int r = 0; r < TC; r++) {
        float v = acc[r] + bias;
        int o = (row0 + r) * 128 + fo;
        if (mode == 0)      g_gate[o] = v;
        else if (mode == 1) {
            float dlt = lg2f(1.0f + ex2f(v * LOG2E)) * LN2;   // softplus
            float d2 = dlt * dlt;
            int ro = (row0 + r) * 512 + fo;
            g_Dp[ro]       = dlt;
            g_Dp[ro + 128] = d2;
            g_Dp[ro + 256] = d2 * dlt;
            g_Dp[ro + 384] = d2 * d2;
        }
        else if (mode == 2) g_bm[o] = v;
        else                g_c [o] = v;
    }
    __syncthreads();   // wpool ready

    if (tid < TC) {
        float p = 0.f;
#pragma unroll
        for (int d = 0; d < 64; d++) p = fmaf(wpool[d], xs[tid * 64 + d], p);
        g_pool[row0 + tid] = p;
    }
}

// ---------------------------------------------------------------------------
// KE: 256 blocks x 512 threads. Warps 0..7: wmma tf32 GEMM [16x512]@[512x128]
//     -> Abar-1 in smem. Then 512-thread segment scan -> cc, ch, P, Q.
// ---------------------------------------------------------------------------
__global__ __launch_bounds__(512, 2) void ke() {
    __shared__ __align__(16) float Dsm[16 * 512];   // 32KB
    __shared__ float abars[TC * 128];               // 8KB   (Abar - 1)
    __shared__ float segP[512];
    __shared__ float segQ[512];

    int tid = threadIdx.x;
    int row0 = blockIdx.x * TC;

    // stage D tile (16 rows x 512) coalesced
    {
        const float4* S = (const float4*)(g_Dp + row0 * 512);
        float4* Dst = (float4*)Dsm;
        for (int i = tid; i < 2048; i += 512) Dst[i] = S[i];
    }
    __syncthreads();

    int w = tid >> 5;
    if (w < 8) {
        wmma::fragment<wmma::matrix_a, 16, 16, 8, wmma::precision::tf32, wmma::row_major> fa;
        wmma::fragment<wmma::matrix_b, 16, 16, 8, wmma::precision::tf32, wmma::row_major> fb;
        wmma::fragment<wmma::accumulator, 16, 16, 8, float> fc;
        wmma::fill_fragment(fc, 0.0f);
        const float* Bp = g_M + w * 16;
#pragma unroll 4
        for (int kk = 0; kk < 64; kk++) {
            wmma::load_matrix_sync(fa, Dsm + kk * 8, 512);
            wmma::load_matrix_sync(fb, Bp + kk * 8 * 128, 128);
#pragma unroll
            for (int t = 0; t < fa.num_elements; t++)
                fa.x[t] = wmma::__float_to_tf32(fa.x[t]);
#pragma unroll
            for (int t = 0; t < fb.num_elements; t++)
                fb.x[t] = wmma::__float_to_tf32(fb.x[t]);
            wmma::mma_sync(fc, fa, fb, fc);
        }
        wmma::store_matrix_sync(abars + w * 16, fc, 128, wmma::mem_row_major);
    }
    __syncthreads();

    // segment scan: thread (s, rq) owns timesteps rq*4..rq*4+3
    int s = tid & 127, rq = tid >> 7;
    float a[4], bp[4];
    {
        float h = 0.f, cA = 1.f;
#pragma unroll
        for (int k = 0; k < 4; k++) {
            int t = rq * 4 + k;
            a[k] = 1.0f + abars[t * 128 + s];
            bp[k] = g_bm[(row0 + t) * 128 + s] * g_pool[row0 + t];
            h = fmaf(a[k], h, bp[k]);
            cA *= a[k];
        }
        segP[rq * 128 + s] = cA;
        segQ[rq * 128 + s] = h;
    }
    __syncthreads();
    {
        float Pp = 1.f, h = 0.f;
#pragma unroll
        for (int j = 0; j < 3; j++) {
            if (j < rq) {
                float pj = segP[j * 128 + s];
                h = fmaf(pj, h, segQ[j * 128 + s]);
                Pp *= pj;
            }
        }
#pragma unroll
        for (int k = 0; k < 4; k++) {
            int t = rq * 4 + k;
            h = fmaf(a[k], h, bp[k]);
            Pp *= a[k];
            float c = g_c[(row0 + t) * 128 + s];
            int off = (row0 + t) * 128 + s;
            g_cc[off] = c * Pp;
            g_ch[off] = c * h;
        }
        if (rq == 3) {
            g_P[blockIdx.x * 128 + s] = Pp;
            g_Q[blockIdx.x * 128 + s] = h;
        }
    }
}

// ---------------------------------------------------------------------------
// KB: 1 block, 512 threads: 64-chunk serial prefix scan.
// ---------------------------------------------------------------------------
__global__ void kb() {
    int tid = threadIdx.x;
    int b = tid >> 7, s = tid & 127;
    int o0 = b * NCH * 128 + s;
    float P[2][8], Q[2][8];
#pragma unroll
    for (int j = 0; j < 8; j++) {
        P[0][j] = g_P[o0 + j * 128];
        Q[0][j] = g_Q[o0 + j * 128];
    }
    float H = 0.f;
    for (int T = 0; T < 8; T++) {
        int cur = T & 1, nxt = cur ^ 1;
        if (T < 7) {
#pragma unroll
            for (int j = 0; j < 8; j++) {
                int o = o0 + ((T + 1) * 8 + j) * 128;
                P[nxt][j] = g_P[o];
                Q[nxt][j] = g_Q[o];
            }
        }
#pragma unroll
        for (int j = 0; j < 8; j++) {
            g_H[o0 + (T * 8 + j) * 128] = H;
            H = fmaf(P[cur][j], H, Q[cur][j]);
        }
    }
}

// ---------------------------------------------------------------------------
// KC: 256 blocks x 512 threads, warp-per-row.
// ---------------------------------------------------------------------------
__global__ __launch_bounds__(512) void kc(const float* __restrict__ x,
                                          const float* __restrict__ Wout,
                                          const float* __restrict__ lnw,
                                          const float* __restrict__ lnb,
                                          float* __restrict__ out) {
    __shared__ float WT2s[128 * 65];
    __shared__ float yis[TC * 128];
    __shared__ float Hs[128];
    int tid = threadIdx.x, lane = tid & 31, w = tid >> 5;
    int row0 = blockIdx.x * TC;

    for (int lin = tid; lin < 8192; lin += 512) {
        int d = lin >> 7, ii = lin & 127;
        WT2s[ii * 65 + d] = Wout[lin];
    }
    if (tid < 128) Hs[tid] = g_H[blockIdx.x * 128 + tid];
    __syncthreads();

    int row = row0 + w;
    {
        float acc = 0.f;
        float gt[4];
#pragma unroll
        for (int q = 0; q < 4; q++) {
            int s = lane + q * 32;
            int off = row * 128 + s;
            acc += g_ch[off] + g_cc[off] * Hs[s];
            gt[q] = g_gate[off];
        }
#pragma unroll
        for (int o = 16; o > 0; o >>= 1) acc += __shfl_xor_sync(0xffffffffu, acc, o);
#pragma unroll
        for (int q = 0; q < 4; q++) {
            int s = lane + q * 32;
            float sig = 1.0f / (1.0f + __expf(-gt[q]));
            yis[w * 128 + s] = acc * gt[q] * sig;
        }
    }
    __syncthreads();

    {
        float acc0 = 0.f, acc1 = 0.f;
#pragma unroll 8
        for (int i = 0; i < 128; i++) {
            float yv = yis[w * 128 + i];
            acc0 = fmaf(WT2s[i * 65 + lane],      yv, acc0);
            acc1 = fmaf(WT2s[i * 65 + lane + 32], yv, acc1);
        }
        float v0 = acc0 + x[row * 64 + lane];
        float v1 = acc1 + x[row * 64 + lane + 32];
        float sv = v0 + v1, sq = v0 * v0 + v1 * v1;
#pragma unroll
        for (int o = 16; o > 0; o >>= 1) {
            sv += __shfl_xor_sync(0xffffffffu, sv, o);
            sq += __shfl_xor_sync(0xffffffffu, sq, o);
        }
        float mu  = sv * (1.0f / 64.0f);
        float var = sq * (1.0f / 64.0f) - mu * mu;
        float inv = rsqrtf(var + 1e-5f);
        out[row * 64 + lane]      = (v0 - mu) * inv * lnw[lane]      + lnb[lane];
        out[row * 64 + lane + 32] = (v1 - mu) * inv * lnw[lane + 32] + lnb[lane + 32];
    }
}

// ---------------------------------------------------------------------------
extern "C" void kernel_launch(void* const* d_in, const int* in_sizes, int n_in,
                              void* d_out, int out_size) {
    const float* x    = (const float*)d_in[0];
    const float* Win  = (const float*)d_in[1];
    const float* Wd   = (const float*)d_in[2];
    const float* bd   = (const float*)d_in[3];
    const float* WB   = (const float*)d_in[4];
    const float* bB   = (const float*)d_in[5];
    const float* WC   = (const float*)d_in[6];
    const float* bC   = (const float*)d_in[7];
    const float* A    = (const float*)d_in[8];
    const float* Wout = (const float*)d_in[9];
    const float* lnw  = (const float*)d_in[10];
    const float* lnb  = (const float*)d_in[11];
    float* out = (float*)d_out;

    kp<<<NROW / TC + 1, 512>>>(x, Win, Wd, bd, WB, bB, WC, bC, A);
    ke<<<NROW / TC, 512>>>();
    kb<<<1, 512>>>();
    kc<<<NROW / TC, 512>>>(x, Wout, lnw, lnb, out);
}

// round 11
// speedup vs baseline: 1.0536x; 1.0536x over previous
#include <cuda_runtime.h>
#include <mma.h>
#include <cstdint>
#include <math.h>

using namespace nvcuda;

// ---------------------------------------------------------------------------
// SelectiveSSM. B=4, L=1024, DM=64, DS=DI=128.
// Abar = mean_i exp(delta_i*A_is) via separable 4-term Taylor == tf32 GEMM:
//   Abar = 1 + Dp @ M,  Dp[r][k*128+i] = delta^(k+1) (tf32),
//                        M[(k*128+i)][s] = A_is^(k+1)/(128 (k+1)!) (tf32)
// KP: projections (gate, delta->tf32 powers, Bm, Cm, x_pool); blk 256 -> M.
// KE: 128 blocks x 32 rows: 16-warp wmma GEMM -> Abar; 2-chunk segment scan
//     -> cc, ch, P, Q.
// KC: 128 blocks x 32 rows: in-block chunk-prefix (H) overlapped with Wout
//     staging, y reduce, silu, paired-row W_out GEMV, residual, LayerNorm.
// ---------------------------------------------------------------------------

#define NB    4
#define NL    1024
#define NROW  4096
#define NCH   64
#define TC    16
#define LOG2E 1.4426950408889634f
#define LN2   0.6931471805599453f

__device__ float g_gate[NROW * 128];
__device__ float g_Dp  [NROW * 512];
__device__ float g_M   [512 * 128];
__device__ float g_bm  [NROW * 128];
__device__ float g_c   [NROW * 128];
__device__ float g_pool[NROW];
__device__ float g_cc  [NROW * 128];
__device__ float g_ch  [NROW * 128];
__device__ float g_P   [NB * NCH * 128];
__device__ float g_Q   [NB * NCH * 128];

__device__ __forceinline__ float ex2f(float v) {
    float r; asm("ex2.approx.ftz.f32 %0, %1;" : "=f"(r) : "f"(v)); return r;
}
__device__ __forceinline__ float lg2f(float v) {
    float r; asm("lg2.approx.ftz.f32 %0, %1;" : "=f"(r) : "f"(v)); return r;
}
__device__ __forceinline__ float tf32r(float v) {
    uint32_t u;
    asm("cvt.rna.tf32.f32 %0, %1;" : "=r"(u) : "f"(v));
    return __uint_as_float(u);
}

// ---------------------------------------------------------------------------
// KP: 257 blocks x 512 threads.
// ---------------------------------------------------------------------------
__global__ __launch_bounds__(512) void kp(
    const float* __restrict__ x,   const float* __restrict__ Win,
    const float* __restrict__ Wd,  const float* __restrict__ bd,
    const float* __restrict__ WB,  const float* __restrict__ bB,
    const float* __restrict__ WC,  const float* __restrict__ bC,
    const float* __restrict__ A) {
    int tid = threadIdx.x;

    if (blockIdx.x == 256) {   // build M (tf32-truncated)
        for (int e = tid; e < 16384; e += 512) {
            float Av = A[e];
            float A2 = Av * Av;
            g_M[e]         = tf32r(Av * (1.0f / 128.0f));
            g_M[16384 + e] = tf32r(A2 * (1.0f / 256.0f));
            g_M[32768 + e] = tf32r(A2 * Av * (1.0f / 768.0f));
            g_M[49152 + e] = tf32r(A2 * A2 * (1.0f / 3072.0f));
        }
        return;
    }

    __shared__ __align__(16) float xs[TC * 64];
    __shared__ float psum[8 * 64];
    __shared__ float wpool[64];

    int row0 = blockIdx.x * TC;

    for (int i = tid; i < TC * 64; i += 512) xs[i] = x[row0 * 64 + i];
    {
        int d = tid & 63, part = tid >> 6;
        float s = 0.f;
        const float* p = Win + part * 16 * 64 + d;
#pragma unroll
        for (int i = 0; i < 16; i++) s += p[i * 64];
        psum[part * 64 + d] = s;
    }
    __syncthreads();

    if (tid < 64) {
        float s = 0.f;
#pragma unroll
        for (int p = 0; p < 8; p++) s += psum[p * 64 + tid];
        wpool[tid] = s * (1.0f / 128.0f);
    }

    int mode = tid >> 7, fo = tid & 127;
    const float* wrow;
    float bias = 0.f;
    if (mode == 0)      { wrow = Win + (128 + fo) * 64; }
    else if (mode == 1) { wrow = Wd + fo * 64; bias = bd[fo]; }
    else if (mode == 2) { wrow = WB + fo * 64; bias = bB[fo]; }
    else                { wrow = WC + fo * 64; bias = bC[fo]; }
    const float4* w4 = (const float4*)wrow;

    float acc[TC];
#pragma unroll
    for (int r = 0; r < TC; r++) acc[r] = 0.f;
#pragma unroll
    for (int d4 = 0; d4 < 16; d4++) {
        float4 wv = __ldg(&w4[d4]);
#pragma unroll
        for (int r = 0; r < TC; r++) {
            float4 xv = *(const float4*)(xs + r * 64 + d4 * 4);
            acc[r] = fmaf(wv.x, xv.x, acc[r]);
            acc[r] = fmaf(wv.y, xv.y, acc[r]);
            acc[r] = fmaf(wv.z, xv.z, acc[r]);
            acc[r] = fmaf(wv.w, xv.w, acc[r]);
        }
    }
#pragma unroll
    for (int r = 0; r < TC; r++) {
        float v = acc[r] + bias;
        int o = (row0 + r) * 128 + fo;
        if (mode == 0)      g_gate[o] = v;
        else if (mode == 1) {
            float dlt = lg2f(1.0f + ex2f(v * LOG2E)) * LN2;   // softplus
            float d2 = dlt * dlt;
            int ro = (row0 + r) * 512 + fo;
            g_Dp[ro]       = tf32r(dlt);
            g_Dp[ro + 128] = tf32r(d2);
            g_Dp[ro + 256] = tf32r(d2 * dlt);
            g_Dp[ro + 384] = tf32r(d2 * d2);
        }
        else if (mode == 2) g_bm[o] = v;
        else                g_c [o] = v;
    }
    __syncthreads();

    if (tid < TC) {
        float p = 0.f;
#pragma unroll
        for (int d = 0; d < 64; d++) p = fmaf(wpool[d], xs[tid * 64 + d], p);
        g_pool[row0 + tid] = p;
    }
}

// ---------------------------------------------------------------------------
// KE: 128 blocks x 512 threads (32 rows = 2 chunks). 16-warp wmma GEMM.
//   dyn smem: Dsm[32*512] | abars[32*128] | segP[8*128] | segQ[8*128] ~88KB
// ---------------------------------------------------------------------------
#define KE_SMEM_FLOATS (16384 + 4096 + 1024 + 1024)

__global__ __launch_bounds__(512) void ke() {
    extern __shared__ __align__(16) float sm[];
    float* Dsm   = sm;                  // 32 x 512 (tf32-patterned)
    float* abars = Dsm + 16384;         // 32 x 128 (Abar - 1)
    float* segP  = abars + 4096;        // 8 x 128
    float* segQ  = segP + 1024;

    int tid = threadIdx.x;
    int row0 = blockIdx.x * 32;

    {
        const float4* S = (const float4*)(g_Dp + row0 * 512);
        float4* D = (float4*)Dsm;
        for (int i = tid; i < 4096; i += 512) D[i] = S[i];
    }
    __syncthreads();

    // GEMM [32 x 512] @ [512 x 128]: warp (mt, nt) -> 16x16 tile
    {
        int w = tid >> 5;
        int mt = w >> 3, nt = w & 7;
        wmma::fragment<wmma::matrix_a, 16, 16, 8, wmma::precision::tf32, wmma::row_major> fa;
        wmma::fragment<wmma::matrix_b, 16, 16, 8, wmma::precision::tf32, wmma::row_major> fb;
        wmma::fragment<wmma::accumulator, 16, 16, 8, float> fc;
        wmma::fill_fragment(fc, 0.0f);
        const float* Ap = Dsm + mt * 16 * 512;
        const float* Bp = g_M + nt * 16;
#pragma unroll 8
        for (int kk = 0; kk < 64; kk++) {
            wmma::load_matrix_sync(fa, Ap + kk * 8, 512);
            wmma::load_matrix_sync(fb, Bp + kk * 8 * 128, 128);
            wmma::mma_sync(fc, fa, fb, fc);
        }
        wmma::store_matrix_sync(abars + mt * 16 * 128 + nt * 16, fc, 128,
                                wmma::mem_row_major);
    }
    __syncthreads();

    // segment scan: thread (s, q) owns segment q (4 steps) of both chunks
    int s = tid & 127, q = tid >> 7;
    float a[2][4], bp[2][4];
#pragma unroll
    for (int c = 0; c < 2; c++) {
        float h = 0.f, cA = 1.f;
#pragma unroll
        for (int k = 0; k < 4; k++) {
            int t = c * 16 + q * 4 + k;
            a[c][k] = 1.0f + abars[t * 128 + s];
            bp[c][k] = g_bm[(row0 + t) * 128 + s] * g_pool[row0 + t];
            h = fmaf(a[c][k], h, bp[c][k]);
            cA *= a[c][k];
        }
        segP[(c * 4 + q) * 128 + s] = cA;
        segQ[(c * 4 + q) * 128 + s] = h;
    }
    __syncthreads();
#pragma unroll
    for (int c = 0; c < 2; c++) {
        float Pp = 1.f, h = 0.f;
#pragma unroll
        for (int j = 0; j < 3; j++) {
            if (j < q) {
                float pj = segP[(c * 4 + j) * 128 + s];
                h = fmaf(pj, h, segQ[(c * 4 + j) * 128 + s]);
                Pp *= pj;
            }
        }
#pragma unroll
        for (int k = 0; k < 4; k++) {
            int t = c * 16 + q * 4 + k;
            h = fmaf(a[c][k], h, bp[c][k]);
            Pp *= a[c][k];
            int off = (row0 + t) * 128 + s;
            float cv = g_c[off];
            g_cc[off] = cv * Pp;
            g_ch[off] = cv * h;
        }
        if (q == 3) {
            int ps = (blockIdx.x * 2 + c) * 128 + s;
            g_P[ps] = Pp;
            g_Q[ps] = h;
        }
    }
}

// ---------------------------------------------------------------------------
// KC: 128 blocks x 512 threads (32 rows = 2 chunks). In-block prefix (warps
//     0-3) overlapped with Wout staging (warps 4-15); warp-per-row y; paired
//     rows in GEMV; warp-private LayerNorm.
//   dyn smem: WT2s[128*65] | yis[32*128] | Hs[2*128]  (~51KB)
// ---------------------------------------------------------------------------
#define KC_SMEM_FLOATS (128 * 65 + 32 * 128 + 2 * 128)

__global__ __launch_bounds__(512) void kc(const float* __restrict__ x,
                                          const float* __restrict__ Wout,
                                          const float* __restrict__ lnw,
                                          const float* __restrict__ lnb,
                                          float* __restrict__ out) {
    extern __shared__ __align__(16) float smc[];
    float* WT2s = smc;                 // 128 x 65 (padded transpose)
    float* yis  = WT2s + 128 * 65;     // 32 x 128
    float* Hs   = yis + 32 * 128;      // 2 x 128

    int tid = threadIdx.x, lane = tid & 31, w = tid >> 5;
    int row0 = blockIdx.x * 32;
    int bb = blockIdx.x >> 5;                 // batch
    int gg0 = (blockIdx.x * 2) & 63;          // first chunk-in-batch

    if (tid >= 128) {
        // warps 4-15: stage Wout transpose
        for (int lin = tid - 128; lin < 8192; lin += 384) {
            int d = lin >> 7, ii = lin & 127;
            WT2s[ii * 65 + d] = Wout[lin];
        }
    } else {
        // warps 0-3: chunk-prefix scan (double-buffered, 8-deep)
        int s = tid;
        int o0 = bb * NCH * 128 + s;
        float P[2][8], Q[2][8];
#pragma unroll
        for (int j = 0; j < 8; j++) {
            P[0][j] = g_P[o0 + j * 128];
            Q[0][j] = g_Q[o0 + j * 128];
        }
        float H = 0.f;
        for (int T = 0; T < 8; T++) {
            int cur = T & 1, nxt = cur ^ 1;
            if (T < 7) {
#pragma unroll
                for (int j = 0; j < 8; j++) {
                    int o = o0 + ((T + 1) * 8 + j) * 128;
                    P[nxt][j] = g_P[o];
                    Q[nxt][j] = g_Q[o];
                }
            }
#pragma unroll
            for (int j = 0; j < 8; j++) {
                int g = T * 8 + j;
                if (g == gg0)     Hs[s]       = H;
                if (g == gg0 + 1) Hs[128 + s] = H;
                H = fmaf(P[cur][j], H, Q[cur][j]);
            }
        }
    }
    __syncthreads();

    // phase A: warp w -> rows w (chunk 0) and w+16 (chunk 1)
#pragma unroll
    for (int c = 0; c < 2; c++) {
        int r = w + c * 16;
        int row = row0 + r;
        float acc = 0.f;
        float gt[4];
#pragma unroll
        for (int qq = 0; qq < 4; qq++) {
            int s = lane + qq * 32;
            int off = row * 128 + s;
            acc += g_ch[off] + g_cc[off] * Hs[c * 128 + s];
            gt[qq] = g_gate[off];
        }
#pragma unroll
        for (int o = 16; o > 0; o >>= 1) acc += __shfl_xor_sync(0xffffffffu, acc, o);
#pragma unroll
        for (int qq = 0; qq < 4; qq++) {
            int s = lane + qq * 32;
            float sig = 1.0f / (1.0f + __expf(-gt[qq]));
            yis[r * 128 + s] = acc * gt[qq] * sig;
        }
    }
    __syncthreads();

    // phase B: warp w -> row pair (2w, 2w+1); lane owns d = lane, lane+32
    {
        int ra = 2 * w, rb = 2 * w + 1;
        float a0 = 0.f, a1 = 0.f, b0 = 0.f, b1 = 0.f;
#pragma unroll 8
        for (int i = 0; i < 128; i++) {
            float w0 = WT2s[i * 65 + lane];
            float w1 = WT2s[i * 65 + lane + 32];
            float ya = yis[ra * 128 + i];
            float yb = yis[rb * 128 + i];
            a0 = fmaf(w0, ya, a0);
            a1 = fmaf(w1, ya, a1);
            b0 = fmaf(w0, yb, b0);
            b1 = fmaf(w1, yb, b1);
        }
        int rowa = row0 + ra, rowb = row0 + rb;
        float va0 = a0 + x[rowa * 64 + lane];
        float va1 = a1 + x[rowa * 64 + lane + 32];
        float vb0 = b0 + x[rowb * 64 + lane];
        float vb1 = b1 + x[rowb * 64 + lane + 32];
        float sva = va0 + va1, sqa = va0 * va0 + va1 * va1;
        float svb = vb0 + vb1, sqb = vb0 * vb0 + vb1 * vb1;
#pragma unroll
        for (int o = 16; o > 0; o >>= 1) {
            sva += __shfl_xor_sync(0xffffffffu, sva, o);
            sqa += __shfl_xor_sync(0xffffffffu, sqa, o);
            svb += __shfl_xor_sync(0xffffffffu, svb, o);
            sqb += __shfl_xor_sync(0xffffffffu, sqb, o);
        }
        float mua  = sva * (1.0f / 64.0f);
        float vara = sqa * (1.0f / 64.0f) - mua * mua;
        float inva = rsqrtf(vara + 1e-5f);
        float mub  = svb * (1.0f / 64.0f);
        float varb = sqb * (1.0f / 64.0f) - mub * mub;
        float invb = rsqrtf(varb + 1e-5f);
        out[rowa * 64 + lane]      = (va0 - mua) * inva * lnw[lane]      + lnb[lane];
        out[rowa * 64 + lane + 32] = (va1 - mua) * inva * lnw[lane + 32] + lnb[lane + 32];
        out[rowb * 64 + lane]      = (vb0 - mub) * invb * lnw[lane]      + lnb[lane];
        out[rowb * 64 + lane + 32] = (vb1 - mub) * invb * lnw[lane + 32] + lnb[lane + 32];
    }
}

// ---------------------------------------------------------------------------
extern "C" void kernel_launch(void* const* d_in, const int* in_sizes, int n_in,
                              void* d_out, int out_size) {
    const float* x    = (const float*)d_in[0];
    const float* Win  = (const float*)d_in[1];
    const float* Wd   = (const float*)d_in[2];
    const float* bd   = (const float*)d_in[3];
    const float* WB   = (const float*)d_in[4];
    const float* bB   = (const float*)d_in[5];
    const float* WC   = (const float*)d_in[6];
    const float* bC   = (const float*)d_in[7];
    const float* A    = (const float*)d_in[8];
    const float* Wout = (const float*)d_in[9];
    const float* lnw  = (const float*)d_in[10];
    const float* lnb  = (const float*)d_in[11];
    float* out = (float*)d_out;

    cudaFuncSetAttribute(ke, cudaFuncAttributeMaxDynamicSharedMemorySize,
                         KE_SMEM_FLOATS * (int)sizeof(float));
    cudaFuncSetAttribute(kc, cudaFuncAttributeMaxDynamicSharedMemorySize,
                         KC_SMEM_FLOATS * (int)sizeof(float));

    kp<<<257, 512>>>(x, Win, Wd, bd, WB, bB, WC, bC, A);
    ke<<<128, 512, KE_SMEM_FLOATS * sizeof(float)>>>();
    kc<<<128, 512, KC_SMEM_FLOATS * sizeof(float)>>>(x, Wout, lnw, lnb, out);
}

// round 12
// speedup vs baseline: 1.0863x; 1.0310x over previous
#include <cuda_runtime.h>
#include <mma.h>
#include <cstdint>
#include <math.h>

using namespace nvcuda;

// ---------------------------------------------------------------------------
// SelectiveSSM. B=4, L=1024, DM=64, DS=DI=128. All three GEMMs on tensor
// cores (tf32):
//   KP: proj [32x64]@[64x512] per block -> gate, delta-powers(tf32), Bm, Cm;
//       x_pool in fp32. Block 128 builds M (Taylor coeff matrix).
//   KE: Abar = 1 + Dp@M  ([32x512]@[512x128]) + 2-chunk segment scan
//       -> cc, ch, P, Q.
//   KC: chunk-prefix (H) , y reduce, silu -> yi; yi@Wout^T ([32x128]@[128x64])
//       on tensor cores; residual + LayerNorm.
// ---------------------------------------------------------------------------

#define NB    4
#define NL    1024
#define NROW  4096
#define NCH   64
#define TC    16
#define LOG2E 1.4426950408889634f
#define LN2   0.6931471805599453f

__device__ float g_gate[NROW * 128];
__device__ float g_Dp  [NROW * 512];
__device__ float g_M   [512 * 128];
__device__ float g_bm  [NROW * 128];
__device__ float g_c   [NROW * 128];
__device__ float g_pool[NROW];
__device__ float g_cc  [NROW * 128];
__device__ float g_ch  [NROW * 128];
__device__ float g_P   [NB * NCH * 128];
__device__ float g_Q   [NB * NCH * 128];

__device__ __forceinline__ float ex2f(float v) {
    float r; asm("ex2.approx.ftz.f32 %0, %1;" : "=f"(r) : "f"(v)); return r;
}
__device__ __forceinline__ float lg2f(float v) {
    float r; asm("lg2.approx.ftz.f32 %0, %1;" : "=f"(r) : "f"(v)); return r;
}
__device__ __forceinline__ float tf32r(float v) {
    uint32_t u;
    asm("cvt.rna.tf32.f32 %0, %1;" : "=r"(u) : "f"(v));
    return __uint_as_float(u);
}

typedef wmma::fragment<wmma::matrix_a, 16, 16, 8, wmma::precision::tf32, wmma::row_major> FragA;
typedef wmma::fragment<wmma::matrix_b, 16, 16, 8, wmma::precision::tf32, wmma::col_major> FragBC;
typedef wmma::fragment<wmma::matrix_b, 16, 16, 8, wmma::precision::tf32, wmma::row_major> FragBR;
typedef wmma::fragment<wmma::accumulator, 16, 16, 8, float> FragC;

template <typename F>
__device__ __forceinline__ void cvt_frag(F& f) {
#pragma unroll
    for (int t = 0; t < f.num_elements; t++) f.x[t] = wmma::__float_to_tf32(f.x[t]);
}

// ---------------------------------------------------------------------------
// KP: 129 blocks x 512 threads. Blocks 0..127: proj GEMM for 32 rows.
//     Block 128: build g_M.
//   dyn smem: xs[32*64] | proj[32*512] | psum[512] | wpool[64]  (~75KB)
// ---------------------------------------------------------------------------
#define KP_SMEM_FLOATS (2048 + 16384 + 512 + 64)

__global__ __launch_bounds__(512) void kp(
    const float* __restrict__ x,   const float* __restrict__ Win,
    const float* __restrict__ Wd,  const float* __restrict__ bd,
    const float* __restrict__ WB,  const float* __restrict__ bB,
    const float* __restrict__ WC,  const float* __restrict__ bC,
    const float* __restrict__ A) {
    int tid = threadIdx.x;

    if (blockIdx.x == 128) {   // build M (tf32-rounded Taylor coefficients)
        for (int e = tid; e < 16384; e += 512) {
            float Av = A[e];
            float A2 = Av * Av;
            g_M[e]         = tf32r(Av * (1.0f / 128.0f));
            g_M[16384 + e] = tf32r(A2 * (1.0f / 256.0f));
            g_M[32768 + e] = tf32r(A2 * Av * (1.0f / 768.0f));
            g_M[49152 + e] = tf32r(A2 * A2 * (1.0f / 3072.0f));
        }
        return;
    }

    extern __shared__ __align__(16) float smp[];
    float* xs    = smp;                // 32 x 64 (fp32)
    float* proj  = xs + 2048;          // 32 x 512
    float* psum  = proj + 16384;       // 8 x 64
    float* wpool = psum + 512;         // 64

    int row0 = blockIdx.x * 32;

    for (int i = tid; i < 2048; i += 512) xs[i] = x[row0 * 64 + i];
    {
        int d = tid & 63, part = tid >> 6;
        float s = 0.f;
        const float* p = Win + part * 16 * 64 + d;
#pragma unroll
        for (int i = 0; i < 16; i++) s += p[i * 64];
        psum[part * 64 + d] = s;
    }
    __syncthreads();

    if (tid < 64) {
        float s = 0.f;
#pragma unroll
        for (int p = 0; p < 8; p++) s += psum[p * 64 + tid];
        wpool[tid] = s * (1.0f / 128.0f);
    }

    // GEMM: warp w -> n-strips {2w, 2w+1}, both m-tiles.  K = 64 (8 steps).
    {
        int w = tid >> 5;
        FragC fc[2][2];
#pragma unroll
        for (int mt = 0; mt < 2; mt++)
#pragma unroll
            for (int j = 0; j < 2; j++) wmma::fill_fragment(fc[mt][j], 0.0f);

        const float* Wp[2];
#pragma unroll
        for (int j = 0; j < 2; j++) {
            int strip = w * 2 + j;
            if (strip < 8)       Wp[j] = Win + (128 + strip * 16) * 64;
            else if (strip < 16) Wp[j] = Wd + (strip - 8) * 16 * 64;
            else if (strip < 24) Wp[j] = WB + (strip - 16) * 16 * 64;
            else                 Wp[j] = WC + (strip - 24) * 16 * 64;
        }

#pragma unroll
        for (int kk = 0; kk < 8; kk++) {
            FragA fa[2];
#pragma unroll
            for (int mt = 0; mt < 2; mt++) {
                wmma::load_matrix_sync(fa[mt], xs + mt * 16 * 64 + kk * 8, 64);
                cvt_frag(fa[mt]);
            }
#pragma unroll
            for (int j = 0; j < 2; j++) {
                FragBC fb;
                wmma::load_matrix_sync(fb, Wp[j] + kk * 8, 64);
                cvt_frag(fb);
#pragma unroll
                for (int mt = 0; mt < 2; mt++)
                    wmma::mma_sync(fc[mt][j], fa[mt], fb, fc[mt][j]);
            }
        }
#pragma unroll
        for (int mt = 0; mt < 2; mt++)
#pragma unroll
            for (int j = 0; j < 2; j++)
                wmma::store_matrix_sync(proj + mt * 16 * 512 + (w * 2 + j) * 16,
                                        fc[mt][j], 512, wmma::mem_row_major);
    }
    __syncthreads();

    // postprocess: thread = feature fo
    {
        int fo = tid, mode = fo >> 7, f = fo & 127;
        float bias = 0.f;
        if (mode == 1)      bias = bd[f];
        else if (mode == 2) bias = bB[f];
        else if (mode == 3) bias = bC[f];

        for (int r = 0; r < 32; r++) {
            float v = proj[r * 512 + fo] + bias;
            int row = row0 + r;
            if (mode == 0)      g_gate[row * 128 + f] = v;
            else if (mode == 1) {
                float dlt = lg2f(1.0f + ex2f(v * LOG2E)) * LN2;   // softplus
                float d2 = dlt * dlt;
                int ro = row * 512 + f;
                g_Dp[ro]       = tf32r(dlt);
                g_Dp[ro + 128] = tf32r(d2);
                g_Dp[ro + 256] = tf32r(d2 * dlt);
                g_Dp[ro + 384] = tf32r(d2 * d2);
            }
            else if (mode == 2) g_bm[row * 128 + f] = v;
            else                g_c [row * 128 + f] = v;
        }
    }

    // x_pool (exact fp32 path)
    if (tid < 32) {
        float p = 0.f;
        const float* xr = xs + tid * 64;
#pragma unroll
        for (int d = 0; d < 64; d++) p = fmaf(wpool[d], xr[d], p);
        g_pool[row0 + tid] = p;
    }
}

// ---------------------------------------------------------------------------
// KE: 128 blocks x 512 threads (32 rows = 2 chunks). 16-warp wmma GEMM.
//   dyn smem: Dsm[32*512] | abars[32*128] | segP[8*128] | segQ[8*128] ~88KB
// ---------------------------------------------------------------------------
#define KE_SMEM_FLOATS (16384 + 4096 + 1024 + 1024)

__global__ __launch_bounds__(512) void ke() {
    extern __shared__ __align__(16) float sm[];
    float* Dsm   = sm;
    float* abars = Dsm + 16384;
    float* segP  = abars + 4096;
    float* segQ  = segP + 1024;

    int tid = threadIdx.x;
    int row0 = blockIdx.x * 32;

    {
        const float4* S = (const float4*)(g_Dp + row0 * 512);
        float4* D = (float4*)Dsm;
        for (int i = tid; i < 4096; i += 512) D[i] = S[i];
    }
    __syncthreads();

    // GEMM [32 x 512] @ [512 x 128]: warp (mt, nt) -> 16x16 tile
    {
        int w = tid >> 5;
        int mt = w >> 3, nt = w & 7;
        FragA fa;
        FragBR fb;
        FragC fc;
        wmma::fill_fragment(fc, 0.0f);
        const float* Ap = Dsm + mt * 16 * 512;
        const float* Bp = g_M + nt * 16;
#pragma unroll 8
        for (int kk = 0; kk < 64; kk++) {
            wmma::load_matrix_sync(fa, Ap + kk * 8, 512);
            wmma::load_matrix_sync(fb, Bp + kk * 8 * 128, 128);
            wmma::mma_sync(fc, fa, fb, fc);
        }
        wmma::store_matrix_sync(abars + mt * 16 * 128 + nt * 16, fc, 128,
                                wmma::mem_row_major);
    }
    __syncthreads();

    // segment scan: thread (s, q) owns segment q (4 steps) of both chunks
    int s = tid & 127, q = tid >> 7;
    float a[2][4], bp[2][4];
#pragma unroll
    for (int c = 0; c < 2; c++) {
        float h = 0.f, cA = 1.f;
#pragma unroll
        for (int k = 0; k < 4; k++) {
            int t = c * 16 + q * 4 + k;
            a[c][k] = 1.0f + abars[t * 128 + s];
            bp[c][k] = g_bm[(row0 + t) * 128 + s] * g_pool[row0 + t];
            h = fmaf(a[c][k], h, bp[c][k]);
            cA *= a[c][k];
        }
        segP[(c * 4 + q) * 128 + s] = cA;
        segQ[(c * 4 + q) * 128 + s] = h;
    }
    __syncthreads();
#pragma unroll
    for (int c = 0; c < 2; c++) {
        float Pp = 1.f, h = 0.f;
#pragma unroll
        for (int j = 0; j < 3; j++) {
            if (j < q) {
                float pj = segP[(c * 4 + j) * 128 + s];
                h = fmaf(pj, h, segQ[(c * 4 + j) * 128 + s]);
                Pp *= pj;
            }
        }
#pragma unroll
        for (int k = 0; k < 4; k++) {
            int t = c * 16 + q * 4 + k;
            h = fmaf(a[c][k], h, bp[c][k]);
            Pp *= a[c][k];
            int off = (row0 + t) * 128 + s;
            float cv = g_c[off];
            g_cc[off] = cv * Pp;
            g_ch[off] = cv * h;
        }
        if (q == 3) {
            int ps = (blockIdx.x * 2 + c) * 128 + s;
            g_P[ps] = Pp;
            g_Q[ps] = h;
        }
    }
}

// ---------------------------------------------------------------------------
// KC: 128 blocks x 512 threads (32 rows = 2 chunks).
//   static smem: yis[32*128] | osm[32*64] | Hs[2*128]  (~25KB)
// ---------------------------------------------------------------------------
__global__ __launch_bounds__(512) void kc(const float* __restrict__ x,
                                          const float* __restrict__ Wout,
                                          const float* __restrict__ lnw,
                                          const float* __restrict__ lnb,
                                          float* __restrict__ out) {
    __shared__ __align__(16) float yis[32 * 128];
    __shared__ __align__(16) float osm[32 * 64];
    __shared__ float Hs[2 * 128];

    int tid = threadIdx.x, lane = tid & 31, w = tid >> 5;
    int row0 = blockIdx.x * 32;
    int bb = blockIdx.x >> 5;                 // batch
    int gg0 = (blockIdx.x * 2) & 63;          // first chunk-in-batch

    if (tid < 128) {
        // warps 0-3: chunk-prefix scan (double-buffered, 8-deep)
        int s = tid;
        int o0 = bb * NCH * 128 + s;
        float P[2][8], Q[2][8];
#pragma unroll
        for (int j = 0; j < 8; j++) {
            P[0][j] = g_P[o0 + j * 128];
            Q[0][j] = g_Q[o0 + j * 128];
        }
        float H = 0.f;
        for (int T = 0; T < 8; T++) {
            int cur = T & 1, nxt = cur ^ 1;
            if (T < 7) {
#pragma unroll
                for (int j = 0; j < 8; j++) {
                    int o = o0 + ((T + 1) * 8 + j) * 128;
                    P[nxt][j] = g_P[o];
                    Q[nxt][j] = g_Q[o];
                }
            }
#pragma unroll
            for (int j = 0; j < 8; j++) {
                int g = T * 8 + j;
                if (g == gg0)     Hs[s]       = H;
                if (g == gg0 + 1) Hs[128 + s] = H;
                H = fmaf(P[cur][j], H, Q[cur][j]);
            }
        }
    }
    __syncthreads();

    // phase A: warp w -> rows w (chunk 0) and w+16 (chunk 1)
#pragma unroll
    for (int c = 0; c < 2; c++) {
        int r = w + c * 16;
        int row = row0 + r;
        float acc = 0.f;
        float gt[4];
#pragma unroll
        for (int qq = 0; qq < 4; qq++) {
            int s = lane + qq * 32;
            int off = row * 128 + s;
            acc += g_ch[off] + g_cc[off] * Hs[c * 128 + s];
            gt[qq] = g_gate[off];
        }
#pragma unroll
        for (int o = 16; o > 0; o >>= 1) acc += __shfl_xor_sync(0xffffffffu, acc, o);
#pragma unroll
        for (int qq = 0; qq < 4; qq++) {
            int s = lane + qq * 32;
            float sig = 1.0f / (1.0f + __expf(-gt[qq]));
            yis[r * 128 + s] = acc * gt[qq] * sig;
        }
    }
    __syncthreads();

    // phase B: GEMM yi[32x128] @ Wout^T[128x64] on warps 0..7
    if (w < 8) {
        int mt = w >> 2, nt = w & 3;
        FragA fa;
        FragBC fb;
        FragC fc;
        wmma::fill_fragment(fc, 0.0f);
        const float* Ap = yis + mt * 16 * 128;
        const float* Bp = Wout + nt * 16 * 128;   // col_major view of Wout^T
#pragma unroll
        for (int kk = 0; kk < 16; kk++) {
            wmma::load_matrix_sync(fa, Ap + kk * 8, 128);
            cvt_frag(fa);
            wmma::load_matrix_sync(fb, Bp + kk * 8, 128);
            cvt_frag(fb);
            wmma::mma_sync(fc, fa, fb, fc);
        }
        wmma::store_matrix_sync(osm + mt * 16 * 64 + nt * 16, fc, 64,
                                wmma::mem_row_major);
    }
    __syncthreads();

    // phase C: warp w -> rows w, w+16; lane owns d = lane, lane+32
#pragma unroll
    for (int c = 0; c < 2; c++) {
        int r = w + c * 16;
        int row = row0 + r;
        float v0 = osm[r * 64 + lane]      + x[row * 64 + lane];
        float v1 = osm[r * 64 + lane + 32] + x[row * 64 + lane + 32];
        float sv = v0 + v1, sq = v0 * v0 + v1 * v1;
#pragma unroll
        for (int o = 16; o > 0; o >>= 1) {
            sv += __shfl_xor_sync(0xffffffffu, sv, o);
            sq += __shfl_xor_sync(0xffffffffu, sq, o);
        }
        float mu  = sv * (1.0f / 64.0f);
        float var = sq * (1.0f / 64.0f) - mu * mu;
        float inv = rsqrtf(var + 1e-5f);
        out[row * 64 + lane]      = (v0 - mu) * inv * lnw[lane]      + lnb[lane];
        out[row * 64 + lane + 32] = (v1 - mu) * inv * lnw[lane + 32] + lnb[lane + 32];
    }
}

// ---------------------------------------------------------------------------
extern "C" void kernel_launch(void* const* d_in, const int* in_sizes, int n_in,
                              void* d_out, int out_size) {
    const float* x    = (const float*)d_in[0];
    const float* Win  = (const float*)d_in[1];
    const float* Wd   = (const float*)d_in[2];
    const float* bd   = (const float*)d_in[3];
    const float* WB   = (const float*)d_in[4];
    const float* bB   = (const float*)d_in[5];
    const float* WC   = (const float*)d_in[6];
    const float* bC   = (const float*)d_in[7];
    const float* A    = (const float*)d_in[8];
    const float* Wout = (const float*)d_in[9];
    const float* lnw  = (const float*)d_in[10];
    const float* lnb  = (const float*)d_in[11];
    float* out = (float*)d_out;

    cudaFuncSetAttribute(kp, cudaFuncAttributeMaxDynamicSharedMemorySize,
                         KP_SMEM_FLOATS * (int)sizeof(float));
    cudaFuncSetAttribute(ke, cudaFuncAttributeMaxDynamicSharedMemorySize,
                         KE_SMEM_FLOATS * (int)sizeof(float));

    kp<<<129, 512, KP_SMEM_FLOATS * sizeof(float)>>>(
        x, Win, Wd, bd, WB, bB, WC, bC, A);
    ke<<<128, 512, KE_SMEM_FLOATS * sizeof(float)>>>();
    kc<<<128, 512>>>(x, Wout, lnw, lnb, out);
}

// round 13
// speedup vs baseline: 1.1239x; 1.0346x over previous
#include <cuda_runtime.h>
#include <mma.h>
#include <cstdint>
#include <math.h>

using namespace nvcuda;

// ---------------------------------------------------------------------------
// SelectiveSSM. B=4, L=1024, DM=64, DS=DI=128.
//   K0:  build M[512x128] = A^k/(128 k!) (tf32), k=1..4.
//   KPE: 256 blocks x 256 thr, 1 chunk (16 rows) each:
//        proj GEMM [16x64]@[64x512] -> gate(out), delta->Dp(in-place smem),
//        Bm/Cm (smem), x_pool; Abar GEMM [16x512]@[512x128] (M from L2);
//        segment scan -> cc, ch, P, Q.
//   KC:  128 blocks x 512 thr: chunk-prefix (H), y reduce, silu -> yi;
//        yi@Wout^T wmma; residual + LayerNorm.
// ---------------------------------------------------------------------------

#define NB    4
#define NL    1024
#define NROW  4096
#define NCH   64
#define TC    16
#define LOG2E 1.4426950408889634f
#define LN2   0.6931471805599453f

__device__ float g_gate[NROW * 128];
__device__ float g_M   [512 * 128];
__device__ float g_cc  [NROW * 128];
__device__ float g_ch  [NROW * 128];
__device__ float g_P   [NB * NCH * 128];
__device__ float g_Q   [NB * NCH * 128];

__device__ __forceinline__ float ex2f(float v) {
    float r; asm("ex2.approx.ftz.f32 %0, %1;" : "=f"(r) : "f"(v)); return r;
}
__device__ __forceinline__ float lg2f(float v) {
    float r; asm("lg2.approx.ftz.f32 %0, %1;" : "=f"(r) : "f"(v)); return r;
}
__device__ __forceinline__ float tf32r(float v) {
    uint32_t u;
    asm("cvt.rna.tf32.f32 %0, %1;" : "=r"(u) : "f"(v));
    return __uint_as_float(u);
}

typedef wmma::fragment<wmma::matrix_a, 16, 16, 8, wmma::precision::tf32, wmma::row_major> FragA;
typedef wmma::fragment<wmma::matrix_b, 16, 16, 8, wmma::precision::tf32, wmma::col_major> FragBC;
typedef wmma::fragment<wmma::matrix_b, 16, 16, 8, wmma::precision::tf32, wmma::row_major> FragBR;
typedef wmma::fragment<wmma::accumulator, 16, 16, 8, float> FragC;

template <typename F>
__device__ __forceinline__ void cvt_frag(F& f) {
#pragma unroll
    for (int t = 0; t < f.num_elements; t++) f.x[t] = wmma::__float_to_tf32(f.x[t]);
}

// ---------------------------------------------------------------------------
// K0: 32 blocks x 512 threads: build M (tf32-rounded Taylor coefficients).
// ---------------------------------------------------------------------------
__global__ void k0(const float* __restrict__ A) {
    int idx = blockIdx.x * 512 + threadIdx.x;
    for (int e = idx; e < 16384; e += 32 * 512) {
        float Av = A[e];
        float A2 = Av * Av;
        g_M[e]         = tf32r(Av * (1.0f / 128.0f));
        g_M[16384 + e] = tf32r(A2 * (1.0f / 256.0f));
        g_M[32768 + e] = tf32r(A2 * Av * (1.0f / 768.0f));
        g_M[49152 + e] = tf32r(A2 * A2 * (1.0f / 3072.0f));
    }
}

// ---------------------------------------------------------------------------
// KPE: 256 blocks x 256 threads (8 warps), 1 chunk each. smem ~63KB.
//   dyn smem: xs[1024] | proj[8192] | bms[2048] | cs[2048] | abars[2048] |
//             segP[256] | segQ[256] | psum[256] | wpool[64] | pools[16]
// ---------------------------------------------------------------------------
#define KPE_SMEM_FLOATS (1024 + 8192 + 2048 + 2048 + 2048 + 256 + 256 + 256 + 64 + 16)

__global__ __launch_bounds__(256) void kpe(
    const float* __restrict__ x,   const float* __restrict__ Win,
    const float* __restrict__ Wd,  const float* __restrict__ bd,
    const float* __restrict__ WB,  const float* __restrict__ bB,
    const float* __restrict__ WC,  const float* __restrict__ bC) {
    extern __shared__ __align__(16) float sm[];
    float* xs    = sm;                 // 16 x 64 (fp32)
    float* proj  = xs + 1024;          // 16 x 512 (proj, then Dp in-place)
    float* bms   = proj + 8192;        // 16 x 128
    float* cs    = bms + 2048;         // 16 x 128
    float* abars = cs + 2048;          // 16 x 128
    float* segP  = abars + 2048;       // 2 x 128
    float* segQ  = segP + 256;         // 2 x 128
    float* psum  = segQ + 256;         // 4 x 64
    float* wpool = psum + 256;         // 64
    float* pools = wpool + 64;         // 16

    int tid = threadIdx.x, w = tid >> 5;
    int row0 = blockIdx.x * TC;

    // ---- phase 0: stage x rows; wpool partial column sums (i < 128 of Win)
    for (int i = tid; i < TC * 64; i += 256) xs[i] = x[row0 * 64 + i];
    {
        int d = tid & 63, part = tid >> 6;   // 4 parts x 32 rows
        float s = 0.f;
        const float* p = Win + part * 32 * 64 + d;
#pragma unroll
        for (int i = 0; i < 32; i++) s += p[i * 64];
        psum[part * 64 + d] = s;
    }
    __syncthreads();

    if (tid < 64) {
        float s = psum[tid] + psum[64 + tid] + psum[128 + tid] + psum[192 + tid];
        wpool[tid] = s * (1.0f / 128.0f);
    }

    // ---- phase 1: proj GEMM [16x64]@[64x512]; warp w -> 4 n-strips
    {
        FragC fc[4];
#pragma unroll
        for (int j = 0; j < 4; j++) wmma::fill_fragment(fc[j], 0.0f);

        const float* Wp[4];
#pragma unroll
        for (int j = 0; j < 4; j++) {
            int st = w * 4 + j;
            if (st < 8)       Wp[j] = Win + (128 + st * 16) * 64;
            else if (st < 16) Wp[j] = Wd + (st - 8) * 16 * 64;
            else if (st < 24) Wp[j] = WB + (st - 16) * 16 * 64;
            else              Wp[j] = WC + (st - 24) * 16 * 64;
        }
#pragma unroll
        for (int kk = 0; kk < 8; kk++) {
            FragA fa;
            wmma::load_matrix_sync(fa, xs + kk * 8, 64);
            cvt_frag(fa);
#pragma unroll
            for (int j = 0; j < 4; j++) {
                FragBC fb;
                wmma::load_matrix_sync(fb, Wp[j] + kk * 8, 64);
                cvt_frag(fb);
                wmma::mma_sync(fc[j], fa, fb, fc[j]);
            }
        }
#pragma unroll
        for (int j = 0; j < 4; j++)
            wmma::store_matrix_sync(proj + (w * 4 + j) * 16, fc[j], 512,
                                    wmma::mem_row_major);
    }
    __syncthreads();

    // ---- phase 2: postprocess. thread -> features tid and tid+256.
    {
        float v1[TC], v2[TC];
#pragma unroll
        for (int r = 0; r < TC; r++) {
            v1[r] = proj[r * 512 + tid];
            v2[r] = proj[r * 512 + tid + 256];
        }
        __syncthreads();   // all reads done before Dp overwrites proj

        if (tid < 128) {
            // fo1 = gate feature tid
#pragma unroll
            for (int r = 0; r < TC; r++)
                g_gate[(row0 + r) * 128 + tid] = v1[r];
            // fo2 = B feature tid
            float bias = bB[tid];
#pragma unroll
            for (int r = 0; r < TC; r++)
                bms[r * 128 + tid] = v2[r] + bias;
        } else {
            int f = tid - 128;
            // fo1 = delta feature f -> softplus powers into proj (Dp layout)
            float bias = bd[f];
#pragma unroll
            for (int r = 0; r < TC; r++) {
                float dlt = lg2f(1.0f + ex2f((v1[r] + bias) * LOG2E)) * LN2;
                float d2 = dlt * dlt;
                proj[r * 512 + f]       = tf32r(dlt);
                proj[r * 512 + 128 + f] = tf32r(d2);
                proj[r * 512 + 256 + f] = tf32r(d2 * dlt);
                proj[r * 512 + 384 + f] = tf32r(d2 * d2);
            }
            // fo2 = C feature f
            float biasC = bC[f];
#pragma unroll
            for (int r = 0; r < TC; r++)
                cs[r * 128 + f] = v2[r] + biasC;
        }
        // x_pool (fp32 exact)
        if (tid < TC) {
            float p = 0.f;
            const float* xr = xs + tid * 64;
#pragma unroll
            for (int d = 0; d < 64; d++) p = fmaf(wpool[d], xr[d], p);
            pools[tid] = p;
        }
    }
    __syncthreads();

    // ---- phase 3: Abar GEMM [16x512]@[512x128]; warp w -> n-tile w
    {
        FragA fa;
        FragBR fb;
        FragC fc;
        wmma::fill_fragment(fc, 0.0f);
        const float* Bp = g_M + w * 16;
#pragma unroll 8
        for (int kk = 0; kk < 64; kk++) {
            wmma::load_matrix_sync(fa, proj + kk * 8, 512);
            wmma::load_matrix_sync(fb, Bp + kk * 8 * 128, 128);
            wmma::mma_sync(fc, fa, fb, fc);
        }
        wmma::store_matrix_sync(abars + w * 16, fc, 128, wmma::mem_row_major);
    }
    __syncthreads();

    // ---- phase 4: segment scan. thread (s, q): 8 timesteps t = q*8+k.
    int s = tid & 127, q = tid >> 7;
    float a[8], bp[8];
    {
        float h = 0.f, cA = 1.f;
#pragma unroll
        for (int k = 0; k < 8; k++) {
            int t = q * 8 + k;
            a[k] = 1.0f + abars[t * 128 + s];
            bp[k] = bms[t * 128 + s] * pools[t];
            h = fmaf(a[k], h, bp[k]);
            cA *= a[k];
        }
        segP[q * 128 + s] = cA;
        segQ[q * 128 + s] = h;
    }
    __syncthreads();
    {
        float Pp = 1.f, h = 0.f;
        if (q == 1) { Pp = segP[s]; h = segQ[s]; }
#pragma unroll
        for (int k = 0; k < 8; k++) {
            int t = q * 8 + k;
            h = fmaf(a[k], h, bp[k]);
            Pp *= a[k];
            int off = (row0 + t) * 128 + s;
            float cv = cs[t * 128 + s];
            g_cc[off] = cv * Pp;
            g_ch[off] = cv * h;
        }
        if (q == 1) {
            g_P[blockIdx.x * 128 + s] = Pp;
            g_Q[blockIdx.x * 128 + s] = h;
        }
    }
}

// ---------------------------------------------------------------------------
// KC: 128 blocks x 512 threads (32 rows = 2 chunks).
// ---------------------------------------------------------------------------
__global__ __launch_bounds__(512) void kc(const float* __restrict__ x,
                                          const float* __restrict__ Wout,
                                          const float* __restrict__ lnw,
                                          const float* __restrict__ lnb,
                                          float* __restrict__ out) {
    __shared__ __align__(16) float yis[32 * 128];
    __shared__ __align__(16) float osm[32 * 64];
    __shared__ float Hs[2 * 128];

    int tid = threadIdx.x, lane = tid & 31, w = tid >> 5;
    int row0 = blockIdx.x * 32;
    int bb = blockIdx.x >> 5;
    int gg0 = (blockIdx.x * 2) & 63;

    if (tid < 128) {
        int s = tid;
        int o0 = bb * NCH * 128 + s;
        float P[2][8], Q[2][8];
#pragma unroll
        for (int j = 0; j < 8; j++) {
            P[0][j] = g_P[o0 + j * 128];
            Q[0][j] = g_Q[o0 + j * 128];
        }
        float H = 0.f;
        for (int T = 0; T < 8; T++) {
            int cur = T & 1, nxt = cur ^ 1;
            if (T < 7) {
#pragma unroll
                for (int j = 0; j < 8; j++) {
                    int o = o0 + ((T + 1) * 8 + j) * 128;
                    P[nxt][j] = g_P[o];
                    Q[nxt][j] = g_Q[o];
                }
            }
#pragma unroll
            for (int j = 0; j < 8; j++) {
                int g = T * 8 + j;
                if (g == gg0)     Hs[s]       = H;
                if (g == gg0 + 1) Hs[128 + s] = H;
                H = fmaf(P[cur][j], H, Q[cur][j]);
            }
        }
    }
    __syncthreads();

    // phase A: warp w -> rows w, w+16
#pragma unroll
    for (int c = 0; c < 2; c++) {
        int r = w + c * 16;
        int row = row0 + r;
        float acc = 0.f;
        float gt[4];
#pragma unroll
        for (int qq = 0; qq < 4; qq++) {
            int s = lane + qq * 32;
            int off = row * 128 + s;
            acc += g_ch[off] + g_cc[off] * Hs[c * 128 + s];
            gt[qq] = g_gate[off];
        }
#pragma unroll
        for (int o = 16; o > 0; o >>= 1) acc += __shfl_xor_sync(0xffffffffu, acc, o);
#pragma unroll
        for (int qq = 0; qq < 4; qq++) {
            int s = lane + qq * 32;
            float sig = 1.0f / (1.0f + __expf(-gt[qq]));
            yis[r * 128 + s] = acc * gt[qq] * sig;
        }
    }
    __syncthreads();

    // phase B: yi[32x128] @ Wout^T[128x64] on warps 0..7
    if (w < 8) {
        int mt = w >> 2, nt = w & 3;
        FragA fa;
        FragBC fb;
        FragC fc;
        wmma::fill_fragment(fc, 0.0f);
        const float* Ap = yis + mt * 16 * 128;
        const float* Bp = Wout + nt * 16 * 128;
#pragma unroll
        for (int kk = 0; kk < 16; kk++) {
            wmma::load_matrix_sync(fa, Ap + kk * 8, 128);
            cvt_frag(fa);
            wmma::load_matrix_sync(fb, Bp + kk * 8, 128);
            cvt_frag(fb);
            wmma::mma_sync(fc, fa, fb, fc);
        }
        wmma::store_matrix_sync(osm + mt * 16 * 64 + nt * 16, fc, 64,
                                wmma::mem_row_major);
    }
    __syncthreads();

    // phase C: residual + warp-private LayerNorm
#pragma unroll
    for (int c = 0; c < 2; c++) {
        int r = w + c * 16;
        int row = row0 + r;
        float v0 = osm[r * 64 + lane]      + x[row * 64 + lane];
        float v1 = osm[r * 64 + lane + 32] + x[row * 64 + lane + 32];
        float sv = v0 + v1, sq = v0 * v0 + v1 * v1;
#pragma unroll
        for (int o = 16; o > 0; o >>= 1) {
            sv += __shfl_xor_sync(0xffffffffu, sv, o);
            sq += __shfl_xor_sync(0xffffffffu, sq, o);
        }
        float mu  = sv * (1.0f / 64.0f);
        float var = sq * (1.0f / 64.0f) - mu * mu;
        float inv = rsqrtf(var + 1e-5f);
        out[row * 64 + lane]      = (v0 - mu) * inv * lnw[lane]      + lnb[lane];
        out[row * 64 + lane + 32] = (v1 - mu) * inv * lnw[lane + 32] + lnb[lane + 32];
    }
}

// ---------------------------------------------------------------------------
extern "C" void kernel_launch(void* const* d_in, const int* in_sizes, int n_in,
                              void* d_out, int out_size) {
    const float* x    = (const float*)d_in[0];
    const float* Win  = (const float*)d_in[1];
    const float* Wd   = (const float*)d_in[2];
    const float* bd   = (const float*)d_in[3];
    const float* WB   = (const float*)d_in[4];
    const float* bB   = (const float*)d_in[5];
    const float* WC   = (const float*)d_in[6];
    const float* bC   = (const float*)d_in[7];
    const float* A    = (const float*)d_in[8];
    const float* Wout = (const float*)d_in[9];
    const float* lnw  = (const float*)d_in[10];
    const float* lnb  = (const float*)d_in[11];
    float* out = (float*)d_out;

    cudaFuncSetAttribute(kpe, cudaFuncAttributeMaxDynamicSharedMemorySize,
                         KPE_SMEM_FLOATS * (int)sizeof(float));

    k0<<<32, 512>>>(A);
    kpe<<<NROW / TC, 256, KPE_SMEM_FLOATS * sizeof(float)>>>(
        x, Win, Wd, bd, WB, bB, WC, bC);
    kc<<<128, 512>>>(x, Wout, lnw, lnb, out);
}

// round 14
// speedup vs baseline: 1.2049x; 1.0721x over previous
#include <cuda_runtime.h>
#include <mma.h>
#include <cstdint>
#include <math.h>

using namespace nvcuda;

// ---------------------------------------------------------------------------
// SelectiveSSM. B=4, L=1024, DM=64, DS=DI=128.
//   K0:  one-time formats: M[512x128]=A^k/(128 k!) tf32; Wt[64x512] stacked
//        weights transposed tf32; WoutT[128x64] tf32; wpool[64].
//   KPE: 128 blocks x 512 thr (32 rows = 2 chunks): proj GEMM
//        [32x64]@[64x512] (B from Wt, no cvt) -> gate/Dp(in-place)/Bm/Cm;
//        x_pool; Abar GEMM [32x512]@[512x128]; dual-chunk segment scan
//        -> cc, ch, P, Q.
//   KC:  128 blocks x 512 thr: chunk-prefix (H), y reduce, silu -> yi (tf32);
//        yi@WoutT wmma (no cvt); residual + LayerNorm.
// ---------------------------------------------------------------------------

#define NB    4
#define NL    1024
#define NROW  4096
#define NCH   64
#define TC    16
#define LOG2E 1.4426950408889634f
#define LN2   0.6931471805599453f

__device__ float g_gate [NROW * 128];
__device__ float g_M    [512 * 128];
__device__ float g_Wt   [64 * 512];
__device__ float g_WoutT[128 * 64];
__device__ float g_wpool[64];
__device__ float g_cc   [NROW * 128];
__device__ float g_ch   [NROW * 128];
__device__ float g_P    [NB * NCH * 128];
__device__ float g_Q    [NB * NCH * 128];

__device__ __forceinline__ float ex2f(float v) {
    float r; asm("ex2.approx.ftz.f32 %0, %1;" : "=f"(r) : "f"(v)); return r;
}
__device__ __forceinline__ float lg2f(float v) {
    float r; asm("lg2.approx.ftz.f32 %0, %1;" : "=f"(r) : "f"(v)); return r;
}
__device__ __forceinline__ float tf32r(float v) {
    uint32_t u;
    asm("cvt.rna.tf32.f32 %0, %1;" : "=r"(u) : "f"(v));
    return __uint_as_float(u);
}

typedef wmma::fragment<wmma::matrix_a, 16, 16, 8, wmma::precision::tf32, wmma::row_major> FragA;
typedef wmma::fragment<wmma::matrix_b, 16, 16, 8, wmma::precision::tf32, wmma::row_major> FragBR;
typedef wmma::fragment<wmma::accumulator, 16, 16, 8, float> FragC;

// ---------------------------------------------------------------------------
// K0: 64 blocks x 256 threads. One-time format conversions.
// ---------------------------------------------------------------------------
__global__ void k0(const float* __restrict__ A,   const float* __restrict__ Win,
                   const float* __restrict__ Wd,  const float* __restrict__ WB,
                   const float* __restrict__ WC,  const float* __restrict__ Wout) {
    int idx = blockIdx.x * 256 + threadIdx.x;
    int stride = 64 * 256;

    // M: Taylor coefficient matrix (tf32)
    for (int e = idx; e < 16384; e += stride) {
        float Av = A[e];
        float A2 = Av * Av;
        g_M[e]         = tf32r(Av * (1.0f / 128.0f));
        g_M[16384 + e] = tf32r(A2 * (1.0f / 256.0f));
        g_M[32768 + e] = tf32r(A2 * Av * (1.0f / 768.0f));
        g_M[49152 + e] = tf32r(A2 * A2 * (1.0f / 3072.0f));
    }
    // Wt[d*512 + n] = Wstack[n][d] (tf32); strips: gate | delta | B | C
    for (int e = idx; e < 64 * 512; e += stride) {
        int d = e >> 9, n = e & 511;
        float v;
        if (n < 128)      v = Win[(128 + n) * 64 + d];
        else if (n < 256) v = Wd [(n - 128) * 64 + d];
        else if (n < 384) v = WB [(n - 256) * 64 + d];
        else              v = WC [(n - 384) * 64 + d];
        g_Wt[e] = tf32r(v);
    }
    // WoutT[i*64 + d] = Wout[d*128 + i] (tf32)
    for (int e = idx; e < 8192; e += stride) {
        int i = e >> 6, d = e & 63;
        g_WoutT[e] = tf32r(Wout[d * 128 + i]);
    }
    // wpool[d] = mean_i Win[i][d]  (exact fp32)
    if (idx < 64) {
        float s = 0.f;
        for (int i = 0; i < 128; i++) s += Win[i * 64 + idx];
        g_wpool[idx] = s * (1.0f / 128.0f);
    }
}

// ---------------------------------------------------------------------------
// KPE: 128 blocks x 512 threads (16 warps). smem ~124KB, single wave.
//   dyn smem: xs[2048] | proj[16384] | bms[4096] | cs[4096] | abars[4096] |
//             segP[512] | segQ[512] | pools[32]
// ---------------------------------------------------------------------------
#define KPE_SMEM_FLOATS (2048 + 16384 + 4096 + 4096 + 4096 + 512 + 512 + 32)

__global__ __launch_bounds__(512) void kpe(
    const float* __restrict__ x,  const float* __restrict__ bd,
    const float* __restrict__ bB, const float* __restrict__ bC) {
    extern __shared__ __align__(16) float sm[];
    float* xs    = sm;                 // 32 x 64 (tf32-patterned)
    float* proj  = xs + 2048;          // 32 x 512 (proj, then Dp in-place)
    float* bms   = proj + 16384;       // 32 x 128
    float* cs    = bms + 4096;         // 32 x 128
    float* abars = cs + 4096;          // 32 x 128
    float* segP  = abars + 4096;       // 4 x 128
    float* segQ  = segP + 512;         // 4 x 128
    float* pools = segQ + 512;         // 32

    int tid = threadIdx.x, w = tid >> 5;
    int row0 = blockIdx.x * 32;

    // stage x rows (tf32-rounded; exact x is re-read in KC for residual)
    for (int i = tid; i < 2048; i += 512) xs[i] = tf32r(x[row0 * 64 + i]);
    __syncthreads();

    // ---- phase 1: proj GEMM [32x64]@[64x512]; warp w -> mt=w>>3, 4 n-tiles
    {
        int mt = w >> 3, nb = (w & 7) * 4;
        FragC fc[4];
#pragma unroll
        for (int j = 0; j < 4; j++) wmma::fill_fragment(fc[j], 0.0f);
#pragma unroll
        for (int kk = 0; kk < 8; kk++) {
            FragA fa;
            wmma::load_matrix_sync(fa, xs + mt * 16 * 64 + kk * 8, 64);
#pragma unroll
            for (int j = 0; j < 4; j++) {
                FragBR fb;
                wmma::load_matrix_sync(fb, g_Wt + kk * 8 * 512 + (nb + j) * 16, 512);
                wmma::mma_sync(fc[j], fa, fb, fc[j]);
            }
        }
#pragma unroll
        for (int j = 0; j < 4; j++)
            wmma::store_matrix_sync(proj + mt * 16 * 512 + (nb + j) * 16,
                                    fc[j], 512, wmma::mem_row_major);
    }
    __syncthreads();

    // ---- phase 2: postprocess. thread = column fo; read all, sync, write.
    {
        int fo = tid;
        float v[32];
#pragma unroll
        for (int r = 0; r < 32; r++) v[r] = proj[r * 512 + fo];
        // x_pool (reads xs, not proj)
        if (tid < 32) {
            float p = 0.f;
            const float* xr = xs + tid * 64;
#pragma unroll
            for (int d = 0; d < 64; d++) p = fmaf(g_wpool[d], xr[d], p);
            pools[tid] = p;
        }
        __syncthreads();   // all proj reads complete before Dp overwrite

        int cls = fo >> 7, f = fo & 127;
        if (cls == 0) {
#pragma unroll
            for (int r = 0; r < 32; r++)
                g_gate[(row0 + r) * 128 + f] = v[r];
        } else if (cls == 1) {
            float bias = bd[f];
#pragma unroll
            for (int r = 0; r < 32; r++) {
                float dlt = lg2f(1.0f + ex2f((v[r] + bias) * LOG2E)) * LN2;
                float d2 = dlt * dlt;
                proj[r * 512 + f]       = tf32r(dlt);
                proj[r * 512 + 128 + f] = tf32r(d2);
                proj[r * 512 + 256 + f] = tf32r(d2 * dlt);
                proj[r * 512 + 384 + f] = tf32r(d2 * d2);
            }
        } else if (cls == 2) {
            float bias = bB[f];
#pragma unroll
            for (int r = 0; r < 32; r++)
                bms[r * 128 + f] = v[r] + bias;
        } else {
            float bias = bC[f];
#pragma unroll
            for (int r = 0; r < 32; r++)
                cs[r * 128 + f] = v[r] + bias;
        }
    }
    __syncthreads();

    // ---- phase 3: Abar GEMM [32x512]@[512x128]; warp w -> (w>>3, w&7)
    {
        int mt = w >> 3, nt = w & 7;
        FragA fa;
        FragBR fb;
        FragC fc;
        wmma::fill_fragment(fc, 0.0f);
#pragma unroll 8
        for (int kk = 0; kk < 64; kk++) {
            wmma::load_matrix_sync(fa, proj + mt * 16 * 512 + kk * 8, 512);
            wmma::load_matrix_sync(fb, g_M + kk * 8 * 128 + nt * 16, 128);
            wmma::mma_sync(fc, fa, fb, fc);
        }
        wmma::store_matrix_sync(abars + mt * 16 * 128 + nt * 16, fc, 128,
                                wmma::mem_row_major);
    }
    __syncthreads();

    // ---- phase 4: segment scan. thread (s, q): chunk c=q>>1, seg=q&1.
    int s = tid & 127, q = tid >> 7;
    int c = q >> 1, seg = q & 1;
    float a[8], bp[8];
    {
        float h = 0.f, cA = 1.f;
#pragma unroll
        for (int k = 0; k < 8; k++) {
            int t = c * 16 + seg * 8 + k;
            a[k] = 1.0f + abars[t * 128 + s];
            bp[k] = bms[t * 128 + s] * pools[t];
            h = fmaf(a[k], h, bp[k]);
            cA *= a[k];
        }
        segP[q * 128 + s] = cA;
        segQ[q * 128 + s] = h;
    }
    __syncthreads();
    {
        float Pp = 1.f, h = 0.f;
        if (seg == 1) { Pp = segP[(c * 2) * 128 + s]; h = segQ[(c * 2) * 128 + s]; }
#pragma unroll
        for (int k = 0; k < 8; k++) {
            int t = c * 16 + seg * 8 + k;
            h = fmaf(a[k], h, bp[k]);
            Pp *= a[k];
            int off = (row0 + t) * 128 + s;
            float cv = cs[t * 128 + s];
            g_cc[off] = cv * Pp;
            g_ch[off] = cv * h;
        }
        if (seg == 1) {
            int ps = (blockIdx.x * 2 + c) * 128 + s;
            g_P[ps] = Pp;
            g_Q[ps] = h;
        }
    }
}

// ---------------------------------------------------------------------------
// KC: 128 blocks x 512 threads (32 rows = 2 chunks).
// ---------------------------------------------------------------------------
__global__ __launch_bounds__(512) void kc(const float* __restrict__ x,
                                          const float* __restrict__ lnw,
                                          const float* __restrict__ lnb,
                                          float* __restrict__ out) {
    __shared__ __align__(16) float yis[32 * 128];
    __shared__ __align__(16) float osm[32 * 64];
    __shared__ float Hs[2 * 128];

    int tid = threadIdx.x, lane = tid & 31, w = tid >> 5;
    int row0 = blockIdx.x * 32;
    int bb = blockIdx.x >> 5;
    int gg0 = (blockIdx.x * 2) & 63;

    if (tid < 128) {
        int s = tid;
        int o0 = bb * NCH * 128 + s;
        float P[2][8], Q[2][8];
#pragma unroll
        for (int j = 0; j < 8; j++) {
            P[0][j] = g_P[o0 + j * 128];
            Q[0][j] = g_Q[o0 + j * 128];
        }
        float H = 0.f;
        for (int T = 0; T < 8; T++) {
            int cur = T & 1, nxt = cur ^ 1;
            if (T < 7) {
#pragma unroll
                for (int j = 0; j < 8; j++) {
                    int o = o0 + ((T + 1) * 8 + j) * 128;
                    P[nxt][j] = g_P[o];
                    Q[nxt][j] = g_Q[o];
                }
            }
#pragma unroll
            for (int j = 0; j < 8; j++) {
                int g = T * 8 + j;
                if (g == gg0)     Hs[s]       = H;
                if (g == gg0 + 1) Hs[128 + s] = H;
                H = fmaf(P[cur][j], H, Q[cur][j]);
            }
        }
    }
    __syncthreads();

    // phase A: warp w -> rows w, w+16; yi stored tf32-rounded
#pragma unroll
    for (int cch = 0; cch < 2; cch++) {
        int r = w + cch * 16;
        int row = row0 + r;
        float acc = 0.f;
        float gt[4];
#pragma unroll
        for (int qq = 0; qq < 4; qq++) {
            int s = lane + qq * 32;
            int off = row * 128 + s;
            acc += g_ch[off] + g_cc[off] * Hs[cch * 128 + s];
            gt[qq] = g_gate[off];
        }
#pragma unroll
        for (int o = 16; o > 0; o >>= 1) acc += __shfl_xor_sync(0xffffffffu, acc, o);
#pragma unroll
        for (int qq = 0; qq < 4; qq++) {
            int s = lane + qq * 32;
            float sig = 1.0f / (1.0f + __expf(-gt[qq]));
            yis[r * 128 + s] = tf32r(acc * gt[qq] * sig);
        }
    }
    __syncthreads();

    // phase B: yi[32x128] @ WoutT[128x64] on warps 0..7 (no cvts)
    if (w < 8) {
        int mt = w >> 2, nt = w & 3;
        FragA fa;
        FragBR fb;
        FragC fc;
        wmma::fill_fragment(fc, 0.0f);
#pragma unroll
        for (int kk = 0; kk < 16; kk++) {
            wmma::load_matrix_sync(fa, yis + mt * 16 * 128 + kk * 8, 128);
            wmma::load_matrix_sync(fb, g_WoutT + kk * 8 * 64 + nt * 16, 64);
            wmma::mma_sync(fc, fa, fb, fc);
        }
        wmma::store_matrix_sync(osm + mt * 16 * 64 + nt * 16, fc, 64,
                                wmma::mem_row_major);
    }
    __syncthreads();

    // phase C: residual + warp-private LayerNorm
#pragma unroll
    for (int cch = 0; cch < 2; cch++) {
        int r = w + cch * 16;
        int row = row0 + r;
        float v0 = osm[r * 64 + lane]      + x[row * 64 + lane];
        float v1 = osm[r * 64 + lane + 32] + x[row * 64 + lane + 32];
        float sv = v0 + v1, sq = v0 * v0 + v1 * v1;
#pragma unroll
        for (int o = 16; o > 0; o >>= 1) {
            sv += __shfl_xor_sync(0xffffffffu, sv, o);
            sq += __shfl_xor_sync(0xffffffffu, sq, o);
        }
        float mu  = sv * (1.0f / 64.0f);
        float var = sq * (1.0f / 64.0f) - mu * mu;
        float inv = rsqrtf(var + 1e-5f);
        out[row * 64 + lane]      = (v0 - mu) * inv * lnw[lane]      + lnb[lane];
        out[row * 64 + lane + 32] = (v1 - mu) * inv * lnw[lane + 32] + lnb[lane + 32];
    }
}

// ---------------------------------------------------------------------------
extern "C" void kernel_launch(void* const* d_in, const int* in_sizes, int n_in,
                              void* d_out, int out_size) {
    const float* x    = (const float*)d_in[0];
    const float* Win  = (const float*)d_in[1];
    const float* Wd   = (const float*)d_in[2];
    const float* bd   = (const float*)d_in[3];
    const float* WB   = (const float*)d_in[4];
    const float* bB   = (const float*)d_in[5];
    const float* WC   = (const float*)d_in[6];
    const float* bC   = (const float*)d_in[7];
    const float* A    = (const float*)d_in[8];
    const float* Wout = (const float*)d_in[9];
    const float* lnw  = (const float*)d_in[10];
    const float* lnb  = (const float*)d_in[11];
    float* out = (float*)d_out;

    cudaFuncSetAttribute(kpe, cudaFuncAttributeMaxDynamicSharedMemorySize,
                         KPE_SMEM_FLOATS * (int)sizeof(float));

    k0<<<64, 256>>>(A, Win, Wd, WB, WC, Wout);
    kpe<<<128, 512, KPE_SMEM_FLOATS * sizeof(float)>>>(x, bd, bB, bC);
    kc<<<128, 512>>>(x, lnw, lnb, out);
}

// round 15
// speedup vs baseline: 1.2134x; 1.0070x over previous
#include <cuda_runtime.h>
#include <mma.h>
#include <cstdint>
#include <math.h>

using namespace nvcuda;

// ---------------------------------------------------------------------------
// SelectiveSSM. B=4, L=1024, DM=64, DS=DI=128.
//   K0:  one-time formats (coalesced-read / scatter-write):
//        M[512x128]=A^k/(128 k!) tf32; Wt[64x512] stacked weights transposed
//        tf32; WoutT[128x64] tf32; wpool[64].
//   KPE: 128 blocks x 512 thr (32 rows = 2 chunks): proj GEMM
//        [32x64]@[64x512] -> gate/Dp(in-place)/Bm/Cm; x_pool; Abar GEMM
//        [32x512]@[512x128]; dual-chunk segment scan -> cc, ch, P, Q.
//   KC:  128 blocks x 512 thr: chunk-prefix (H), vectorized y reduce, silu
//        -> yi (tf32); yi@WoutT wmma; residual + LayerNorm.
// ---------------------------------------------------------------------------

#define NB    4
#define NL    1024
#define NROW  4096
#define NCH   64
#define TC    16
#define LOG2E 1.4426950408889634f
#define LN2   0.6931471805599453f

__device__ float g_gate [NROW * 128];
__device__ float g_M    [512 * 128];
__device__ float g_Wt   [64 * 512];
__device__ float g_WoutT[128 * 64];
__device__ float g_wpool[64];
__device__ float g_cc   [NROW * 128];
__device__ float g_ch   [NROW * 128];
__device__ float g_P    [NB * NCH * 128];
__device__ float g_Q    [NB * NCH * 128];

__device__ __forceinline__ float ex2f(float v) {
    float r; asm("ex2.approx.ftz.f32 %0, %1;" : "=f"(r) : "f"(v)); return r;
}
__device__ __forceinline__ float lg2f(float v) {
    float r; asm("lg2.approx.ftz.f32 %0, %1;" : "=f"(r) : "f"(v)); return r;
}
__device__ __forceinline__ float tf32r(float v) {
    uint32_t u;
    asm("cvt.rna.tf32.f32 %0, %1;" : "=r"(u) : "f"(v));
    return __uint_as_float(u);
}

typedef wmma::fragment<wmma::matrix_a, 16, 16, 8, wmma::precision::tf32, wmma::row_major> FragA;
typedef wmma::fragment<wmma::matrix_b, 16, 16, 8, wmma::precision::tf32, wmma::row_major> FragBR;
typedef wmma::fragment<wmma::accumulator, 16, 16, 8, float> FragC;

// ---------------------------------------------------------------------------
// K0: 96 blocks x 512 threads. Coalesced reads, scattered writes.
//   warps 0..1023:    Wt  — warp (n = gw & 511, half = gw >> 9): read 32
//                     contiguous floats of weight row n, scatter to column n.
//   warps 1024..1279: WoutT — warp (d = g2 >> 2, q = g2 & 3): read contiguous,
//                     scatter.
//   all blocks:       M via grid-stride float4.
//   block 95:         wpool (block-local psum reduction).
// ---------------------------------------------------------------------------
__global__ __launch_bounds__(512) void k0(
    const float* __restrict__ A,   const float* __restrict__ Win,
    const float* __restrict__ Wd,  const float* __restrict__ WB,
    const float* __restrict__ WC,  const float* __restrict__ Wout) {
    int tid = threadIdx.x, lane = tid & 31;
    int gw = blockIdx.x * 16 + (tid >> 5);

    // M: Taylor coefficient matrix (tf32), float4 both sides
    {
        const float4* A4 = (const float4*)A;
        int idx = blockIdx.x * 512 + tid;
        for (int e4 = idx; e4 < 4096; e4 += 96 * 512) {
            float4 av = A4[e4];
            float4 m1, m2, m3, m4;
            float a2x = av.x * av.x, a2y = av.y * av.y,
                  a2z = av.z * av.z, a2w = av.w * av.w;
            m1.x = tf32r(av.x * (1.0f / 128.0f));
            m1.y = tf32r(av.y * (1.0f / 128.0f));
            m1.z = tf32r(av.z * (1.0f / 128.0f));
            m1.w = tf32r(av.w * (1.0f / 128.0f));
            m2.x = tf32r(a2x * (1.0f / 256.0f));
            m2.y = tf32r(a2y * (1.0f / 256.0f));
            m2.z = tf32r(a2z * (1.0f / 256.0f));
            m2.w = tf32r(a2w * (1.0f / 256.0f));
            m3.x = tf32r(a2x * av.x * (1.0f / 768.0f));
            m3.y = tf32r(a2y * av.y * (1.0f / 768.0f));
            m3.z = tf32r(a2z * av.z * (1.0f / 768.0f));
            m3.w = tf32r(a2w * av.w * (1.0f / 768.0f));
            m4.x = tf32r(a2x * a2x * (1.0f / 3072.0f));
            m4.y = tf32r(a2y * a2y * (1.0f / 3072.0f));
            m4.z = tf32r(a2z * a2z * (1.0f / 3072.0f));
            m4.w = tf32r(a2w * a2w * (1.0f / 3072.0f));
            ((float4*)g_M)[e4]        = m1;
            ((float4*)g_M)[4096 + e4] = m2;
            ((float4*)g_M)[8192 + e4] = m3;
            ((float4*)g_M)[12288 + e4] = m4;
        }
    }

    if (gw < 1024) {
        // Wt: warp handles column n, d-range [half*32, half*32+32)
        int n = gw & 511, half = gw >> 9;
        const float* src;
        if (n < 128)      src = Win + (128 + n) * 64;
        else if (n < 256) src = Wd + (n - 128) * 64;
        else if (n < 384) src = WB + (n - 256) * 64;
        else              src = WC + (n - 384) * 64;
        int d = half * 32 + lane;
        g_Wt[d * 512 + n] = tf32r(src[d]);          // coalesced read, scatter write
    } else if (gw < 1280) {
        // WoutT: warp handles (d, quarter): i-range [q*32, q*32+32)
        int g2 = gw - 1024;
        int d = g2 >> 2, q = g2 & 3;
        int i = q * 32 + lane;
        g_WoutT[i * 64 + d] = tf32r(Wout[d * 128 + i]);
    }

    // wpool: block 95, full 512 threads
    if (blockIdx.x == 95) {
        __shared__ float psum[8 * 64];
        int d = tid & 63, part = tid >> 6;
        float s = 0.f;
        const float* p = Win + part * 16 * 64 + d;
#pragma unroll
        for (int i = 0; i < 16; i++) s += p[i * 64];
        psum[part * 64 + d] = s;
        __syncthreads();
        if (tid < 64) {
            float t = 0.f;
#pragma unroll
            for (int p8 = 0; p8 < 8; p8++) t += psum[p8 * 64 + tid];
            g_wpool[tid] = t * (1.0f / 128.0f);
        }
    }
}

// ---------------------------------------------------------------------------
// KPE: 128 blocks x 512 threads (16 warps). smem ~124KB, single wave.
//   dyn smem: xs[2048] | proj[16384] | bms[4096] | cs[4096] | abars[4096] |
//             segP[512] | segQ[512] | pools[32]
// ---------------------------------------------------------------------------
#define KPE_SMEM_FLOATS (2048 + 16384 + 4096 + 4096 + 4096 + 512 + 512 + 32)

__global__ __launch_bounds__(512) void kpe(
    const float* __restrict__ x,  const float* __restrict__ bd,
    const float* __restrict__ bB, const float* __restrict__ bC) {
    extern __shared__ __align__(16) float sm[];
    float* xs    = sm;                 // 32 x 64 (tf32-patterned)
    float* proj  = xs + 2048;          // 32 x 512 (proj, then Dp in-place)
    float* bms   = proj + 16384;       // 32 x 128
    float* cs    = bms + 4096;         // 32 x 128
    float* abars = cs + 4096;          // 32 x 128
    float* segP  = abars + 4096;       // 4 x 128
    float* segQ  = segP + 512;         // 4 x 128
    float* pools = segQ + 512;         // 32

    int tid = threadIdx.x, w = tid >> 5;
    int row0 = blockIdx.x * 32;

    for (int i = tid; i < 2048; i += 512) xs[i] = tf32r(x[row0 * 64 + i]);
    __syncthreads();

    // ---- phase 1: proj GEMM [32x64]@[64x512]
    {
        int mt = w >> 3, nb = (w & 7) * 4;
        FragC fc[4];
#pragma unroll
        for (int j = 0; j < 4; j++) wmma::fill_fragment(fc[j], 0.0f);
#pragma unroll
        for (int kk = 0; kk < 8; kk++) {
            FragA fa;
            wmma::load_matrix_sync(fa, xs + mt * 16 * 64 + kk * 8, 64);
#pragma unroll
            for (int j = 0; j < 4; j++) {
                FragBR fb;
                wmma::load_matrix_sync(fb, g_Wt + kk * 8 * 512 + (nb + j) * 16, 512);
                wmma::mma_sync(fc[j], fa, fb, fc[j]);
            }
        }
#pragma unroll
        for (int j = 0; j < 4; j++)
            wmma::store_matrix_sync(proj + mt * 16 * 512 + (nb + j) * 16,
                                    fc[j], 512, wmma::mem_row_major);
    }
    __syncthreads();

    // ---- phase 2: postprocess. thread = column fo; read all, sync, write.
    {
        int fo = tid;
        float v[32];
#pragma unroll
        for (int r = 0; r < 32; r++) v[r] = proj[r * 512 + fo];
        if (tid < 32) {
            float p = 0.f;
            const float* xr = xs + tid * 64;
#pragma unroll
            for (int d = 0; d < 64; d++) p = fmaf(g_wpool[d], xr[d], p);
            pools[tid] = p;
        }
        __syncthreads();   // all proj reads complete before Dp overwrite

        int cls = fo >> 7, f = fo & 127;
        if (cls == 0) {
#pragma unroll
            for (int r = 0; r < 32; r++)
                g_gate[(row0 + r) * 128 + f] = v[r];
        } else if (cls == 1) {
            float bias = bd[f];
#pragma unroll
            for (int r = 0; r < 32; r++) {
                float dlt = lg2f(1.0f + ex2f((v[r] + bias) * LOG2E)) * LN2;
                float d2 = dlt * dlt;
                proj[r * 512 + f]       = tf32r(dlt);
                proj[r * 512 + 128 + f] = tf32r(d2);
                proj[r * 512 + 256 + f] = tf32r(d2 * dlt);
                proj[r * 512 + 384 + f] = tf32r(d2 * d2);
            }
        } else if (cls == 2) {
            float bias = bB[f];
#pragma unroll
            for (int r = 0; r < 32; r++)
                bms[r * 128 + f] = v[r] + bias;
        } else {
            float bias = bC[f];
#pragma unroll
            for (int r = 0; r < 32; r++)
                cs[r * 128 + f] = v[r] + bias;
        }
    }
    __syncthreads();

    // ---- phase 3: Abar GEMM [32x512]@[512x128]
    {
        int mt = w >> 3, nt = w & 7;
        FragA fa;
        FragBR fb;
        FragC fc;
        wmma::fill_fragment(fc, 0.0f);
#pragma unroll 8
        for (int kk = 0; kk < 64; kk++) {
            wmma::load_matrix_sync(fa, proj + mt * 16 * 512 + kk * 8, 512);
            wmma::load_matrix_sync(fb, g_M + kk * 8 * 128 + nt * 16, 128);
            wmma::mma_sync(fc, fa, fb, fc);
        }
        wmma::store_matrix_sync(abars + mt * 16 * 128 + nt * 16, fc, 128,
                                wmma::mem_row_major);
    }
    __syncthreads();

    // ---- phase 4: segment scan. thread (s, q): chunk c=q>>1, seg=q&1.
    int s = tid & 127, q = tid >> 7;
    int c = q >> 1, seg = q & 1;
    float a[8], bp[8];
    {
        float h = 0.f, cA = 1.f;
#pragma unroll
        for (int k = 0; k < 8; k++) {
            int t = c * 16 + seg * 8 + k;
            a[k] = 1.0f + abars[t * 128 + s];
            bp[k] = bms[t * 128 + s] * pools[t];
            h = fmaf(a[k], h, bp[k]);
            cA *= a[k];
        }
        segP[q * 128 + s] = cA;
        segQ[q * 128 + s] = h;
    }
    __syncthreads();
    {
        float Pp = 1.f, h = 0.f;
        if (seg == 1) { Pp = segP[(c * 2) * 128 + s]; h = segQ[(c * 2) * 128 + s]; }
#pragma unroll
        for (int k = 0; k < 8; k++) {
            int t = c * 16 + seg * 8 + k;
            h = fmaf(a[k], h, bp[k]);
            Pp *= a[k];
            int off = (row0 + t) * 128 + s;
            float cv = cs[t * 128 + s];
            g_cc[off] = cv * Pp;
            g_ch[off] = cv * h;
        }
        if (seg == 1) {
            int ps = (blockIdx.x * 2 + c) * 128 + s;
            g_P[ps] = Pp;
            g_Q[ps] = h;
        }
    }
}

// ---------------------------------------------------------------------------
// KC: 128 blocks x 512 threads (32 rows = 2 chunks). Vectorized phase A.
// ---------------------------------------------------------------------------
__global__ __launch_bounds__(512) void kc(const float* __restrict__ x,
                                          const float* __restrict__ lnw,
                                          const float* __restrict__ lnb,
                                          float* __restrict__ out) {
    __shared__ __align__(16) float yis[32 * 128];
    __shared__ __align__(16) float osm[32 * 64];
    __shared__ __align__(16) float Hs[2 * 128];

    int tid = threadIdx.x, lane = tid & 31, w = tid >> 5;
    int row0 = blockIdx.x * 32;
    int bb = blockIdx.x >> 5;
    int gg0 = (blockIdx.x * 2) & 63;

    if (tid < 128) {
        int s = tid;
        int o0 = bb * NCH * 128 + s;
        float P[2][8], Q[2][8];
#pragma unroll
        for (int j = 0; j < 8; j++) {
            P[0][j] = g_P[o0 + j * 128];
            Q[0][j] = g_Q[o0 + j * 128];
        }
        float H = 0.f;
        for (int T = 0; T < 8; T++) {
            int cur = T & 1, nxt = cur ^ 1;
            if (T < 7) {
#pragma unroll
                for (int j = 0; j < 8; j++) {
                    int o = o0 + ((T + 1) * 8 + j) * 128;
                    P[nxt][j] = g_P[o];
                    Q[nxt][j] = g_Q[o];
                }
            }
#pragma unroll
            for (int j = 0; j < 8; j++) {
                int g = T * 8 + j;
                if (g == gg0)     Hs[s]       = H;
                if (g == gg0 + 1) Hs[128 + s] = H;
                H = fmaf(P[cur][j], H, Q[cur][j]);
            }
        }
    }
    __syncthreads();

    // phase A (vectorized): warp w -> rows w, w+16; lane owns s = lane*4..+3
#pragma unroll
    for (int cch = 0; cch < 2; cch++) {
        int r = w + cch * 16;
        int row = row0 + r;
        float4 chv = ((const float4*)(g_ch + row * 128))[lane];
        float4 ccv = ((const float4*)(g_cc + row * 128))[lane];
        float4 gtv = ((const float4*)(g_gate + row * 128))[lane];
        float4 hv  = ((const float4*)(Hs + cch * 128))[lane];
        float acc = (chv.x + ccv.x * hv.x) + (chv.y + ccv.y * hv.y)
                  + (chv.z + ccv.z * hv.z) + (chv.w + ccv.w * hv.w);
#pragma unroll
        for (int o = 16; o > 0; o >>= 1) acc += __shfl_xor_sync(0xffffffffu, acc, o);
        float4 yv;
        yv.x = tf32r(acc * gtv.x / (1.0f + __expf(-gtv.x)));
        yv.y = tf32r(acc * gtv.y / (1.0f + __expf(-gtv.y)));
        yv.z = tf32r(acc * gtv.z / (1.0f + __expf(-gtv.z)));
        yv.w = tf32r(acc * gtv.w / (1.0f + __expf(-gtv.w)));
        ((float4*)(yis + r * 128))[lane] = yv;
    }
    __syncthreads();

    // phase B: yi[32x128] @ WoutT[128x64] on warps 0..7
    if (w < 8) {
        int mt = w >> 2, nt = w & 3;
        FragA fa;
        FragBR fb;
        FragC fc;
        wmma::fill_fragment(fc, 0.0f);
#pragma unroll
        for (int kk = 0; kk < 16; kk++) {
            wmma::load_matrix_sync(fa, yis + mt * 16 * 128 + kk * 8, 128);
            wmma::load_matrix_sync(fb, g_WoutT + kk * 8 * 64 + nt * 16, 64);
            wmma::mma_sync(fc, fa, fb, fc);
        }
        wmma::store_matrix_sync(osm + mt * 16 * 64 + nt * 16, fc, 64,
                                wmma::mem_row_major);
    }
    __syncthreads();

    // phase C: residual + warp-private LayerNorm
#pragma unroll
    for (int cch = 0; cch < 2; cch++) {
        int r = w + cch * 16;
        int row = row0 + r;
        float v0 = osm[r * 64 + lane]      + x[row * 64 + lane];
        float v1 = osm[r * 64 + lane + 32] + x[row * 64 + lane + 32];
        float sv = v0 + v1, sq = v0 * v0 + v1 * v1;
#pragma unroll
        for (int o = 16; o > 0; o >>= 1) {
            sv += __shfl_xor_sync(0xffffffffu, sv, o);
            sq += __shfl_xor_sync(0xffffffffu, sq, o);
        }
        float mu  = sv * (1.0f / 64.0f);
        float var = sq * (1.0f / 64.0f) - mu * mu;
        float inv = rsqrtf(var + 1e-5f);
        out[row * 64 + lane]      = (v0 - mu) * inv * lnw[lane]      + lnb[lane];
        out[row * 64 + lane + 32] = (v1 - mu) * inv * lnw[lane + 32] + lnb[lane + 32];
    }
}

// ---------------------------------------------------------------------------
extern "C" void kernel_launch(void* const* d_in, const int* in_sizes, int n_in,
                              void* d_out, int out_size) {
    const float* x    = (const float*)d_in[0];
    const float* Win  = (const float*)d_in[1];
    const float* Wd   = (const float*)d_in[2];
    const float* bd   = (const float*)d_in[3];
    const float* WB   = (const float*)d_in[4];
    const float* bB   = (const float*)d_in[5];
    const float* WC   = (const float*)d_in[6];
    const float* bC   = (const float*)d_in[7];
    const float* A    = (const float*)d_in[8];
    const float* Wout = (const float*)d_in[9];
    const float* lnw  = (const float*)d_in[10];
    const float* lnb  = (const float*)d_in[11];
    float* out = (float*)d_out;

    cudaFuncSetAttribute(kpe, cudaFuncAttributeMaxDynamicSharedMemorySize,
                         KPE_SMEM_FLOATS * (int)sizeof(float));

    k0<<<96, 512>>>(A, Win, Wd, WB, WC, Wout);
    kpe<<<128, 512, KPE_SMEM_FLOATS * sizeof(float)>>>(x, bd, bB, bC);
    kc<<<128, 512>>>(x, lnw, lnb, out);
}

// round 16
// speedup vs baseline: 1.2940x; 1.0664x over previous
#include <cuda_runtime.h>
#include <mma.h>
#include <cstdint>
#include <math.h>

using namespace nvcuda;

// ---------------------------------------------------------------------------
// SelectiveSSM, SINGLE fused kernel. B=4, L=1024, DM=64, DS=DI=128.
// 128 blocks x 512 threads (all co-resident) with 2 device-wide barriers:
//   A: format M[512x128] (Taylor tf32), Wt[64x512], WoutT[128x64], wpool.
//   -- devbar --
//   B: per block = 32 rows = 2 chunks: proj GEMM [32x64]@[64x512];
//      postprocess -> gate/cc-inputs in SMEM, Dp in-place; Abar GEMM
//      [32x512]@[512x128]; segment scan -> cc,ch (SMEM), P,Q (global).
//   -- devbar (threadfence) --
//   C: in-block chunk prefix -> H; y reduce (smem), silu -> yi; yi@WoutT
//      wmma; residual + LayerNorm -> out.
// ---------------------------------------------------------------------------

#define NB    4
#define NL    1024
#define NROW  4096
#define NCH   64
#define LOG2E 1.4426950408889634f
#define LN2   0.6931471805599453f
#define NBLK  128

__device__ float g_M    [512 * 128];
__device__ float g_Wt   [64 * 512];
__device__ float g_WoutT[128 * 64];
__device__ float g_wpool[64];
__device__ float g_P    [NB * NCH * 128];
__device__ float g_Q    [NB * NCH * 128];
__device__ unsigned g_cnt = 0;
__device__ unsigned g_sense = 0;

__device__ __forceinline__ float ex2f(float v) {
    float r; asm("ex2.approx.ftz.f32 %0, %1;" : "=f"(r) : "f"(v)); return r;
}
__device__ __forceinline__ float lg2f(float v) {
    float r; asm("lg2.approx.ftz.f32 %0, %1;" : "=f"(r) : "f"(v)); return r;
}
__device__ __forceinline__ float tf32r(float v) {
    uint32_t u;
    asm("cvt.rna.tf32.f32 %0, %1;" : "=r"(u) : "f"(v));
    return __uint_as_float(u);
}

// sense-reversing device barrier; graph-replay safe (sense only increments).
__device__ __forceinline__ void devbar() {
    __syncthreads();
    if (threadIdx.x == 0) {
        __threadfence();
        unsigned s = atomicAdd(&g_sense, 0u);       // read current sense
        unsigned old = atomicAdd(&g_cnt, 1u);
        if (old == NBLK - 1) {
            g_cnt = 0;                               // no concurrent arrivers
            __threadfence();
            atomicAdd(&g_sense, 1u);                 // release
        } else {
            while (atomicAdd(&g_sense, 0u) == s) __nanosleep(64);
        }
    }
    __syncthreads();
}

typedef wmma::fragment<wmma::matrix_a, 16, 16, 8, wmma::precision::tf32, wmma::row_major> FragA;
typedef wmma::fragment<wmma::matrix_b, 16, 16, 8, wmma::precision::tf32, wmma::row_major> FragBR;
typedef wmma::fragment<wmma::accumulator, 16, 16, 8, float> FragC;

// dynamic smem layout (floats):
//   xs[2048] | gate[4096] | ccs[4096] | chs[4096] | bms[4096] | cs[4096] |
//   abars[4096] | proj[16384] | segP[512] | segQ[512] | pools[32]
// kc scratch (yis[4096] | osm[2048] | Hs[256]) unions into proj.
#define SMEM_FLOATS (2048 + 4096 * 6 + 16384 + 512 + 512 + 32)

__global__ __launch_bounds__(512) void fused(
    const float* __restrict__ x,   const float* __restrict__ Win,
    const float* __restrict__ Wd,  const float* __restrict__ bd,
    const float* __restrict__ WB,  const float* __restrict__ bB,
    const float* __restrict__ WC,  const float* __restrict__ bC,
    const float* __restrict__ A,   const float* __restrict__ Wout,
    const float* __restrict__ lnw, const float* __restrict__ lnb,
    float* __restrict__ out) {
    extern __shared__ __align__(16) float sm[];
    float* xs    = sm;                 // 32 x 64 (tf32-patterned)
    float* gate  = xs + 2048;          // 32 x 128
    float* ccs   = gate + 4096;        // 32 x 128  c*cumA
    float* chs   = ccs + 4096;         // 32 x 128  c*h_loc
    float* bms   = chs + 4096;         // 32 x 128
    float* cs    = bms + 4096;         // 32 x 128
    float* abars = cs + 4096;          // 32 x 128
    float* proj  = abars + 4096;       // 32 x 512 (proj -> Dp; later kc scratch)
    float* segP  = proj + 16384;       // 4 x 128
    float* segQ  = segP + 512;         // 4 x 128
    float* pools = segQ + 512;         // 32
    // kc overlay inside proj:
    float* yis = proj;                 // 32 x 128
    float* osm = proj + 4096;          // 32 x 64
    float* Hs  = proj + 6144;          // 2 x 128

    int tid = threadIdx.x, lane = tid & 31, w = tid >> 5;
    int bid = blockIdx.x;
    int row0 = bid * 32;

    // ======================= Section A: formats =======================
    {
        // M (first 8 blocks, float4 both sides)
        int idx = bid * 512 + tid;
        if (idx < 4096) {
            const float4* A4 = (const float4*)A;
            float4 av = A4[idx];
            float a2x = av.x * av.x, a2y = av.y * av.y,
                  a2z = av.z * av.z, a2w = av.w * av.w;
            float4 m1 = { tf32r(av.x * (1.0f / 128.0f)), tf32r(av.y * (1.0f / 128.0f)),
                          tf32r(av.z * (1.0f / 128.0f)), tf32r(av.w * (1.0f / 128.0f)) };
            float4 m2 = { tf32r(a2x * (1.0f / 256.0f)), tf32r(a2y * (1.0f / 256.0f)),
                          tf32r(a2z * (1.0f / 256.0f)), tf32r(a2w * (1.0f / 256.0f)) };
            float4 m3 = { tf32r(a2x * av.x * (1.0f / 768.0f)), tf32r(a2y * av.y * (1.0f / 768.0f)),
                          tf32r(a2z * av.z * (1.0f / 768.0f)), tf32r(a2w * av.w * (1.0f / 768.0f)) };
            float4 m4 = { tf32r(a2x * a2x * (1.0f / 3072.0f)), tf32r(a2y * a2y * (1.0f / 3072.0f)),
                          tf32r(a2z * a2z * (1.0f / 3072.0f)), tf32r(a2w * a2w * (1.0f / 3072.0f)) };
            ((float4*)g_M)[idx]         = m1;
            ((float4*)g_M)[4096 + idx]  = m2;
            ((float4*)g_M)[8192 + idx]  = m3;
            ((float4*)g_M)[12288 + idx] = m4;
        }
        // Wt: warp task gw < 1024 -> (n, half); coalesced read, scatter write
        int gw = bid * 16 + w;
        if (gw < 1024) {
            int n = gw & 511, half = gw >> 9;
            const float* src;
            if (n < 128)      src = Win + (128 + n) * 64;
            else if (n < 256) src = Wd + (n - 128) * 64;
            else if (n < 384) src = WB + (n - 256) * 64;
            else              src = WC + (n - 384) * 64;
            int d = half * 32 + lane;
            g_Wt[d * 512 + n] = tf32r(src[d]);
        } else if (gw < 1280) {
            int g2 = gw - 1024;
            int d = g2 >> 2, q = g2 & 3;
            int i = q * 32 + lane;
            g_WoutT[i * 64 + d] = tf32r(Wout[d * 128 + i]);
        }
        // wpool: block 127 (psum in segP/segQ scratch, pre-B usage)
        if (bid == 127) {
            float* psum = segP;   // 512 floats scratch
            int d = tid & 63, part = tid >> 6;
            float s = 0.f;
            const float* p = Win + part * 16 * 64 + d;
#pragma unroll
            for (int i = 0; i < 16; i++) s += p[i * 64];
            psum[part * 64 + d] = s;
            __syncthreads();
            if (tid < 64) {
                float t = 0.f;
#pragma unroll
                for (int p8 = 0; p8 < 8; p8++) t += psum[p8 * 64 + tid];
                g_wpool[tid] = t * (1.0f / 128.0f);
            }
        }
    }
    devbar();

    // ======================= Section B: proj + Abar + scan ============
    for (int i = tid; i < 2048; i += 512) xs[i] = tf32r(x[row0 * 64 + i]);
    __syncthreads();

    // proj GEMM [32x64]@[64x512]
    {
        int mt = w >> 3, nb = (w & 7) * 4;
        FragC fc[4];
#pragma unroll
        for (int j = 0; j < 4; j++) wmma::fill_fragment(fc[j], 0.0f);
#pragma unroll
        for (int kk = 0; kk < 8; kk++) {
            FragA fa;
            wmma::load_matrix_sync(fa, xs + mt * 16 * 64 + kk * 8, 64);
#pragma unroll
            for (int j = 0; j < 4; j++) {
                FragBR fb;
                wmma::load_matrix_sync(fb, g_Wt + kk * 8 * 512 + (nb + j) * 16, 512);
                wmma::mma_sync(fc[j], fa, fb, fc[j]);
            }
        }
#pragma unroll
        for (int j = 0; j < 4; j++)
            wmma::store_matrix_sync(proj + mt * 16 * 512 + (nb + j) * 16,
                                    fc[j], 512, wmma::mem_row_major);
    }
    __syncthreads();

    // postprocess: thread = column fo; read all, sync, write.
    {
        int fo = tid;
        float v[32];
#pragma unroll
        for (int r = 0; r < 32; r++) v[r] = proj[r * 512 + fo];
        if (tid < 32) {
            float p = 0.f;
            const float* xr = xs + tid * 64;
#pragma unroll
            for (int d = 0; d < 64; d++) p = fmaf(g_wpool[d], xr[d], p);
            pools[tid] = p;
        }
        __syncthreads();   // proj reads complete before Dp overwrite

        int cls = fo >> 7, f = fo & 127;
        if (cls == 0) {
#pragma unroll
            for (int r = 0; r < 32; r++) gate[r * 128 + f] = v[r];
        } else if (cls == 1) {
            float bias = bd[f];
#pragma unroll
            for (int r = 0; r < 32; r++) {
                float dlt = lg2f(1.0f + ex2f((v[r] + bias) * LOG2E)) * LN2;
                float d2 = dlt * dlt;
                proj[r * 512 + f]       = tf32r(dlt);
                proj[r * 512 + 128 + f] = tf32r(d2);
                proj[r * 512 + 256 + f] = tf32r(d2 * dlt);
                proj[r * 512 + 384 + f] = tf32r(d2 * d2);
            }
        } else if (cls == 2) {
            float bias = bB[f];
#pragma unroll
            for (int r = 0; r < 32; r++) bms[r * 128 + f] = v[r] + bias;
        } else {
            float bias = bC[f];
#pragma unroll
            for (int r = 0; r < 32; r++) cs[r * 128 + f] = v[r] + bias;
        }
    }
    __syncthreads();

    // Abar GEMM [32x512]@[512x128]
    {
        int mt = w >> 3, nt = w & 7;
        FragA fa;
        FragBR fb;
        FragC fc;
        wmma::fill_fragment(fc, 0.0f);
#pragma unroll 8
        for (int kk = 0; kk < 64; kk++) {
            wmma::load_matrix_sync(fa, proj + mt * 16 * 512 + kk * 8, 512);
            wmma::load_matrix_sync(fb, g_M + kk * 8 * 128 + nt * 16, 128);
            wmma::mma_sync(fc, fa, fb, fc);
        }
        wmma::store_matrix_sync(abars + mt * 16 * 128 + nt * 16, fc, 128,
                                wmma::mem_row_major);
    }
    __syncthreads();

    // segment scan: thread (s, q); chunk c = q>>1, seg = q&1; 8 steps each.
    {
        int s = tid & 127, q = tid >> 7;
        int c = q >> 1, seg = q & 1;
        float a[8], bp[8];
        float h = 0.f, cA = 1.f;
#pragma unroll
        for (int k = 0; k < 8; k++) {
            int t = c * 16 + seg * 8 + k;
            a[k] = 1.0f + abars[t * 128 + s];
            bp[k] = bms[t * 128 + s] * pools[t];
            h = fmaf(a[k], h, bp[k]);
            cA *= a[k];
        }
        segP[q * 128 + s] = cA;
        segQ[q * 128 + s] = h;
        __syncthreads();

        float Pp = 1.f;
        h = 0.f;
        if (seg == 1) { Pp = segP[(c * 2) * 128 + s]; h = segQ[(c * 2) * 128 + s]; }
#pragma unroll
        for (int k = 0; k < 8; k++) {
            int t = c * 16 + seg * 8 + k;
            h = fmaf(a[k], h, bp[k]);
            Pp *= a[k];
            float cv = cs[t * 128 + s];
            ccs[t * 128 + s] = cv * Pp;
            chs[t * 128 + s] = cv * h;
        }
        if (seg == 1) {
            int ps = (bid * 2 + c) * 128 + s;
            g_P[ps] = Pp;
            g_Q[ps] = h;
        }
    }
    devbar();   // publishes P/Q chip-wide (threadfence inside)

    // ======================= Section C: output ========================
    int bb = bid >> 5;                  // batch
    int gg0 = (bid * 2) & 63;           // first chunk-in-batch

    if (tid < 128) {
        int s = tid;
        int o0 = bb * NCH * 128 + s;
        float P[2][8], Q[2][8];
#pragma unroll
        for (int j = 0; j < 8; j++) {
            P[0][j] = g_P[o0 + j * 128];
            Q[0][j] = g_Q[o0 + j * 128];
        }
        float H = 0.f;
        for (int T = 0; T < 8; T++) {
            int cur = T & 1, nxt = cur ^ 1;
            if (T < 7) {
#pragma unroll
                for (int j = 0; j < 8; j++) {
                    int o = o0 + ((T + 1) * 8 + j) * 128;
                    P[nxt][j] = g_P[o];
                    Q[nxt][j] = g_Q[o];
                }
            }
#pragma unroll
            for (int j = 0; j < 8; j++) {
                int g = T * 8 + j;
                if (g == gg0)     Hs[s]       = H;
                if (g == gg0 + 1) Hs[128 + s] = H;
                H = fmaf(P[cur][j], H, Q[cur][j]);
            }
        }
    }
    __syncthreads();

    // y reduce + silu -> yi (overlays proj; gate/ccs/chs live elsewhere)
#pragma unroll
    for (int cch = 0; cch < 2; cch++) {
        int r = w + cch * 16;
        float4 chv = ((const float4*)(chs + r * 128))[lane];
        float4 ccv = ((const float4*)(ccs + r * 128))[lane];
        float4 gtv = ((const float4*)(gate + r * 128))[lane];
        float4 hv  = ((const float4*)(Hs + cch * 128))[lane];
        float acc = (chv.x + ccv.x * hv.x) + (chv.y + ccv.y * hv.y)
                  + (chv.z + ccv.z * hv.z) + (chv.w + ccv.w * hv.w);
#pragma unroll
        for (int o = 16; o > 0; o >>= 1) acc += __shfl_xor_sync(0xffffffffu, acc, o);
        float4 yv;
        yv.x = tf32r(acc * gtv.x / (1.0f + __expf(-gtv.x)));
        yv.y = tf32r(acc * gtv.y / (1.0f + __expf(-gtv.y)));
        yv.z = tf32r(acc * gtv.z / (1.0f + __expf(-gtv.z)));
        yv.w = tf32r(acc * gtv.w / (1.0f + __expf(-gtv.w)));
        ((float4*)(yis + r * 128))[lane] = yv;
    }
    __syncthreads();

    // yi[32x128] @ WoutT[128x64] on warps 0..7
    if (w < 8) {
        int mt = w >> 2, nt = w & 3;
        FragA fa;
        FragBR fb;
        FragC fc;
        wmma::fill_fragment(fc, 0.0f);
#pragma unroll
        for (int kk = 0; kk < 16; kk++) {
            wmma::load_matrix_sync(fa, yis + mt * 16 * 128 + kk * 8, 128);
            wmma::load_matrix_sync(fb, g_WoutT + kk * 8 * 64 + nt * 16, 64);
            wmma::mma_sync(fc, fa, fb, fc);
        }
        wmma::store_matrix_sync(osm + mt * 16 * 64 + nt * 16, fc, 64,
                                wmma::mem_row_major);
    }
    __syncthreads();

    // residual + warp-private LayerNorm
#pragma unroll
    for (int cch = 0; cch < 2; cch++) {
        int r = w + cch * 16;
        int row = row0 + r;
        float v0 = osm[r * 64 + lane]      + x[row * 64 + lane];
        float v1 = osm[r * 64 + lane + 32] + x[row * 64 + lane + 32];
        float sv = v0 + v1, sq = v0 * v0 + v1 * v1;
#pragma unroll
        for (int o = 16; o > 0; o >>= 1) {
            sv += __shfl_xor_sync(0xffffffffu, sv, o);
            sq += __shfl_xor_sync(0xffffffffu, sq, o);
        }
        float mu  = sv * (1.0f / 64.0f);
        float var = sq * (1.0f / 64.0f) - mu * mu;
        float inv = rsqrtf(var + 1e-5f);
        out[row * 64 + lane]      = (v0 - mu) * inv * lnw[lane]      + lnb[lane];
        out[row * 64 + lane + 32] = (v1 - mu) * inv * lnw[lane + 32] + lnb[lane + 32];
    }
}

// ---------------------------------------------------------------------------
extern "C" void kernel_launch(void* const* d_in, const int* in_sizes, int n_in,
                              void* d_out, int out_size) {
    const float* x    = (const float*)d_in[0];
    const float* Win  = (const float*)d_in[1];
    const float* Wd   = (const float*)d_in[2];
    const float* bd   = (const float*)d_in[3];
    const float* WB   = (const float*)d_in[4];
    const float* bB   = (const float*)d_in[5];
    const float* WC   = (const float*)d_in[6];
    const float* bC   = (const float*)d_in[7];
    const float* A    = (const float*)d_in[8];
    const float* Wout = (const float*)d_in[9];
    const float* lnw  = (const float*)d_in[10];
    const float* lnb  = (const float*)d_in[11];
    float* out = (float*)d_out;

    cudaFuncSetAttribute(fused, cudaFuncAttributeMaxDynamicSharedMemorySize,
                         SMEM_FLOATS * (int)sizeof(float));

    fused<<<NBLK, 512, SMEM_FLOATS * sizeof(float)>>>(
        x, Win, Wd, bd, WB, bB, WC, bC, A, Wout, lnw, lnb, out);
}